// round 1
// baseline (speedup 1.0000x reference)
#include <cuda_runtime.h>
#include <math.h>

#define B_   16
#define LK_  2048
#define LQ_  256
#define DIM_ 512
#define H_   8
#define DK_  64

// scratch (allocation-free rule: __device__ globals)
__device__ float g_q[B_ * LQ_ * DIM_];   // 8 MB: Q projection result
__device__ float g_x[B_ * LQ_ * DIM_];   // 8 MB: attention output (pre-Wo)

// ---------------------------------------------------------------------------
// GEMM: C[M,512] = A[M,512] @ W[512,512] + bias,  M = 4096
// BM=128, BN=128, BK=32, 256 threads, 8x8 register tile per thread
// ---------------------------------------------------------------------------
__global__ __launch_bounds__(256, 2)
void gemm_bias_kernel(const float* __restrict__ A, const float* __restrict__ W,
                      const float* __restrict__ bias, float* __restrict__ C) {
    __shared__ float As[32 * 132];   // As[k][m], padded stride 132
    __shared__ float Ws[32 * 132];   // Ws[k][n], padded stride 132

    const int tid = threadIdx.x;
    const int tx  = tid & 15;   // n-group
    const int ty  = tid >> 4;   // m-group
    const int n0  = blockIdx.x * 128;
    const int m0  = blockIdx.y * 128;

    float acc[8][8];
    #pragma unroll
    for (int i = 0; i < 8; ++i)
        #pragma unroll
        for (int j = 0; j < 8; ++j) acc[i][j] = 0.f;

    for (int kb = 0; kb < DIM_; kb += 32) {
        // A tile 128x32 -> transposed As[k][m]
        {
            const int r  = tid >> 3;         // 0..31
            const int kc = (tid & 7) * 4;    // 0..28
            #pragma unroll
            for (int it = 0; it < 4; ++it) {
                int m = r + it * 32;
                float4 v = *(const float4*)&A[(size_t)(m0 + m) * DIM_ + kb + kc];
                As[(kc + 0) * 132 + m] = v.x;
                As[(kc + 1) * 132 + m] = v.y;
                As[(kc + 2) * 132 + m] = v.z;
                As[(kc + 3) * 132 + m] = v.w;
            }
        }
        // W tile 32x128 -> Ws[k][n]
        {
            const int k = tid >> 5;          // 0..7
            const int n = (tid & 31) * 4;    // 0..124
            #pragma unroll
            for (int it = 0; it < 4; ++it) {
                float4 v = *(const float4*)&W[(size_t)(kb + k + it * 8) * DIM_ + n0 + n];
                *(float4*)&Ws[(k + it * 8) * 132 + n] = v;
            }
        }
        __syncthreads();

        #pragma unroll
        for (int k = 0; k < 32; ++k) {
            float4 a0 = *(const float4*)&As[k * 132 + ty * 8];
            float4 a1 = *(const float4*)&As[k * 132 + ty * 8 + 4];
            float4 w0 = *(const float4*)&Ws[k * 132 + tx * 8];
            float4 w1 = *(const float4*)&Ws[k * 132 + tx * 8 + 4];
            float a[8] = {a0.x, a0.y, a0.z, a0.w, a1.x, a1.y, a1.z, a1.w};
            float w[8] = {w0.x, w0.y, w0.z, w0.w, w1.x, w1.y, w1.z, w1.w};
            #pragma unroll
            for (int i = 0; i < 8; ++i)
                #pragma unroll
                for (int j = 0; j < 8; ++j)
                    acc[i][j] += a[i] * w[j];
        }
        __syncthreads();
    }

    // epilogue with bias, vectorized stores
    float4 b0 = *(const float4*)&bias[n0 + tx * 8];
    float4 b1 = *(const float4*)&bias[n0 + tx * 8 + 4];
    #pragma unroll
    for (int i = 0; i < 8; ++i) {
        size_t row = (size_t)(m0 + ty * 8 + i) * DIM_ + n0 + tx * 8;
        float4 o0 = make_float4(acc[i][0] + b0.x, acc[i][1] + b0.y,
                                acc[i][2] + b0.z, acc[i][3] + b0.w);
        float4 o1 = make_float4(acc[i][4] + b1.x, acc[i][5] + b1.y,
                                acc[i][6] + b1.z, acc[i][7] + b1.w);
        *(float4*)&C[row]     = o0;
        *(float4*)&C[row + 4] = o1;
    }
}

// ---------------------------------------------------------------------------
// Flash attention: per CTA one (b, h, 64-row q block); K tile = 128 rows.
// K/Q stored d-major in smem; K uses an XOR swizzle at float4-group
// granularity so both GEMM read directions are conflict-free:
//   word(d,k) = d*128 + (((k>>2) ^ (d&31)) << 2) + (k&3)
// ---------------------------------------------------------------------------
#define ATTN_SMEM_FLOATS (64 * 64 + 64 * 128 + 64 * 132)
#define ATTN_SMEM_BYTES  (ATTN_SMEM_FLOATS * 4)

__global__ __launch_bounds__(256, 2)
void attn_kernel(const float* __restrict__ Lp, const float* __restrict__ Qp,
                 float* __restrict__ Xp) {
    extern __shared__ float smem[];
    float* Qs = smem;                  // [64 d][64 q]
    float* Ks = smem + 64 * 64;        // swizzled [64 d][128 k]
    float* Ps = Ks + 64 * 128;         // [64 q][132]   (P row-major, padded)

    const int tid = threadIdx.x;
    const int tx  = tid & 15;          // k-group (S) / d-group (PV, O)
    const int ty  = tid >> 4;          // q-group: rows ty*4 .. ty*4+3
    const int qb  = blockIdx.x;        // 0..3
    const int h   = blockIdx.y;        // 0..7
    const int b   = blockIdx.z;        // 0..15

    const float scale = 0.00552427172801990775f;  // 1/(8*sqrt(512))

    // ---- load Q tile (64 x 64), pre-scaled, transposed into Qs[d][q] ----
    {
        const int r  = tid >> 4;
        const int d0 = (tid & 15) * 4;
        const float* qbase = Qp + ((size_t)b * LQ_ + (size_t)qb * 64) * DIM_ + h * DK_;
        #pragma unroll
        for (int it = 0; it < 4; ++it) {
            int row = r + it * 16;
            float4 v = *(const float4*)&qbase[(size_t)row * DIM_ + d0];
            Qs[(d0 + 0) * 64 + row] = v.x * scale;
            Qs[(d0 + 1) * 64 + row] = v.y * scale;
            Qs[(d0 + 2) * 64 + row] = v.z * scale;
            Qs[(d0 + 3) * 64 + row] = v.w * scale;
        }
    }

    float o[4][4];
    float m_[4], l_[4];
    #pragma unroll
    for (int i = 0; i < 4; ++i) {
        m_[i] = -1.0e30f; l_[i] = 0.f;
        #pragma unroll
        for (int j = 0; j < 4; ++j) o[i][j] = 0.f;
    }

    const float* lbase = Lp + (size_t)b * LK_ * DIM_ + h * DK_;

    for (int kt = 0; kt < LK_ / 128; ++kt) {
        __syncthreads();   // Ks/Ps reuse barrier (also covers Q-load on iter 0)

        // ---- load K tile (128 rows x 64 d) into swizzled Ks ----
        {
            const int r  = tid >> 4;
            const int d0 = (tid & 15) * 4;
            #pragma unroll
            for (int it = 0; it < 8; ++it) {
                int row = r + it * 16;
                float4 v = *(const float4*)&lbase[(size_t)(kt * 128 + row) * DIM_ + d0];
                int kg = row >> 2, kc = row & 3;
                Ks[(d0 + 0) * 128 + ((kg ^ ((d0 + 0) & 31)) << 2) + kc] = v.x;
                Ks[(d0 + 1) * 128 + ((kg ^ ((d0 + 1) & 31)) << 2) + kc] = v.y;
                Ks[(d0 + 2) * 128 + ((kg ^ ((d0 + 2) & 31)) << 2) + kc] = v.z;
                Ks[(d0 + 3) * 128 + ((kg ^ ((d0 + 3) & 31)) << 2) + kc] = v.w;
            }
        }
        __syncthreads();

        // ---- S = (scaled Q) K^T : s[4 q][8 k], k cols = tx*8 + j ----
        float s[4][8];
        #pragma unroll
        for (int i = 0; i < 4; ++i)
            #pragma unroll
            for (int j = 0; j < 8; ++j) s[i][j] = 0.f;

        #pragma unroll 8
        for (int d = 0; d < 64; ++d) {
            const int dx = d & 31;
            float4 qv = *(const float4*)&Qs[d * 64 + ty * 4];
            float4 k0 = *(const float4*)&Ks[d * 128 + (((2 * tx + 0) ^ dx) << 2)];
            float4 k1 = *(const float4*)&Ks[d * 128 + (((2 * tx + 1) ^ dx) << 2)];
            float qa[4] = {qv.x, qv.y, qv.z, qv.w};
            float ka[8] = {k0.x, k0.y, k0.z, k0.w, k1.x, k1.y, k1.z, k1.w};
            #pragma unroll
            for (int i = 0; i < 4; ++i)
                #pragma unroll
                for (int j = 0; j < 8; ++j)
                    s[i][j] += qa[i] * ka[j];
        }

        // ---- online softmax (row reduce across the 16 tx lanes) ----
        #pragma unroll
        for (int i = 0; i < 4; ++i) {
            float rm = s[i][0];
            #pragma unroll
            for (int j = 1; j < 8; ++j) rm = fmaxf(rm, s[i][j]);
            rm = fmaxf(rm, __shfl_xor_sync(0xffffffffu, rm, 8));
            rm = fmaxf(rm, __shfl_xor_sync(0xffffffffu, rm, 4));
            rm = fmaxf(rm, __shfl_xor_sync(0xffffffffu, rm, 2));
            rm = fmaxf(rm, __shfl_xor_sync(0xffffffffu, rm, 1));
            float mn    = fmaxf(m_[i], rm);
            float alpha = __expf(m_[i] - mn);
            float p[8];
            float rs = 0.f;
            #pragma unroll
            for (int j = 0; j < 8; ++j) { p[j] = __expf(s[i][j] - mn); rs += p[j]; }
            rs += __shfl_xor_sync(0xffffffffu, rs, 8);
            rs += __shfl_xor_sync(0xffffffffu, rs, 4);
            rs += __shfl_xor_sync(0xffffffffu, rs, 2);
            rs += __shfl_xor_sync(0xffffffffu, rs, 1);
            l_[i] = l_[i] * alpha + rs;
            m_[i] = mn;
            #pragma unroll
            for (int j = 0; j < 4; ++j) o[i][j] *= alpha;
            *(float4*)&Ps[(ty * 4 + i) * 132 + tx * 8]     = make_float4(p[0], p[1], p[2], p[3]);
            *(float4*)&Ps[(ty * 4 + i) * 132 + tx * 8 + 4] = make_float4(p[4], p[5], p[6], p[7]);
        }
        __syncthreads();

        // ---- O += P V   (V == K tile, read d-major from swizzled Ks) ----
        int dgb[4], dgx[4];
        #pragma unroll
        for (int dj = 0; dj < 4; ++dj) {
            int d = tx * 4 + dj;
            dgb[dj] = d * 128;
            dgx[dj] = d & 31;
        }
        #pragma unroll 4
        for (int kk4 = 0; kk4 < 32; ++kk4) {
            float4 vv[4];
            #pragma unroll
            for (int dj = 0; dj < 4; ++dj)
                vv[dj] = *(const float4*)&Ks[dgb[dj] + ((kk4 ^ dgx[dj]) << 2)];
            #pragma unroll
            for (int i = 0; i < 4; ++i) {
                float4 pp = *(const float4*)&Ps[(ty * 4 + i) * 132 + (kk4 << 2)];
                #pragma unroll
                for (int dj = 0; dj < 4; ++dj) {
                    o[i][dj] += pp.x * vv[dj].x;
                    o[i][dj] += pp.y * vv[dj].y;
                    o[i][dj] += pp.z * vv[dj].z;
                    o[i][dj] += pp.w * vv[dj].w;
                }
            }
        }
    }

    // ---- epilogue: normalize and store x[b, q, h*64 + d] ----
    #pragma unroll
    for (int i = 0; i < 4; ++i) {
        float inv = 1.f / l_[i];
        size_t row = (size_t)b * LQ_ + (size_t)qb * 64 + ty * 4 + i;
        float4 ov = make_float4(o[i][0] * inv, o[i][1] * inv,
                                o[i][2] * inv, o[i][3] * inv);
        *(float4*)&Xp[row * DIM_ + h * DK_ + tx * 4] = ov;
    }
}

// ---------------------------------------------------------------------------
extern "C" void kernel_launch(void* const* d_in, const int* in_sizes, int n_in,
                              void* d_out, int out_size) {
    const float* L  = (const float*)d_in[0];
    const float* G  = (const float*)d_in[1];
    const float* Wq = (const float*)d_in[2];
    const float* bq = (const float*)d_in[3];
    const float* Wo = (const float*)d_in[4];
    const float* bo = (const float*)d_in[5];
    float* out = (float*)d_out;

    float *qbuf, *xbuf;
    cudaGetSymbolAddress((void**)&qbuf, g_q);
    cudaGetSymbolAddress((void**)&xbuf, g_x);

    cudaFuncSetAttribute(attn_kernel,
                         cudaFuncAttributeMaxDynamicSharedMemorySize,
                         ATTN_SMEM_BYTES);

    dim3 gProj(DIM_ / 128, (B_ * LQ_) / 128);   // (4, 32) = 128 CTAs
    dim3 gAttn(LQ_ / 64, H_, B_);               // (4, 8, 16) = 512 CTAs

    gemm_bias_kernel<<<gProj, 256>>>(G, Wq, bq, qbuf);
    attn_kernel<<<gAttn, 256, ATTN_SMEM_BYTES>>>(L, qbuf, xbuf);
    gemm_bias_kernel<<<gProj, 256>>>(xbuf, Wo, bo, out);
}

// round 2
// speedup vs baseline: 1.0025x; 1.0025x over previous
#include <cuda_runtime.h>
#include <math.h>

#define B_   16
#define LK_  2048
#define LQ_  256
#define DIM_ 512
#define H_   8
#define DK_  64

typedef unsigned long long u64x2;   // packed f32x2

__device__ __forceinline__ u64x2 dup2(float v) {
    u64x2 r; asm("mov.b64 %0, {%1, %1};" : "=l"(r) : "f"(v)); return r;
}
__device__ __forceinline__ float2 unpk2(u64x2 v) {
    float2 f; asm("mov.b64 {%0, %1}, %2;" : "=f"(f.x), "=f"(f.y) : "l"(v)); return f;
}
__device__ __forceinline__ void fma2(u64x2& d, u64x2 a, u64x2 b) {
    asm("fma.rn.f32x2 %0, %1, %2, %0;" : "+l"(d) : "l"(a), "l"(b));
}
__device__ __forceinline__ void mul2(u64x2& d, u64x2 a) {
    asm("mul.rn.f32x2 %0, %0, %1;" : "+l"(d) : "l"(a));
}

// scratch (allocation-free rule: __device__ globals)
__device__ float g_q[B_ * LQ_ * DIM_];
__device__ float g_x[B_ * LQ_ * DIM_];

// ---------------------------------------------------------------------------
// GEMM: C[M,512] = A[M,512] @ W[512,512] + bias,  M = 4096
// BM=128, BN=128, BK=32, 256 threads, 8x8 per thread via f32x2 (packed n)
// ---------------------------------------------------------------------------
__global__ __launch_bounds__(256, 2)
void gemm_bias_kernel(const float* __restrict__ A, const float* __restrict__ W,
                      const float* __restrict__ bias, float* __restrict__ C) {
    __shared__ float As[32 * 132];
    __shared__ float Ws[32 * 132];

    const int tid = threadIdx.x;
    const int tx  = tid & 15;
    const int ty  = tid >> 4;
    const int n0  = blockIdx.x * 128;
    const int m0  = blockIdx.y * 128;

    u64x2 acc[8][4];   // 8 m-rows x 4 n-pairs
    #pragma unroll
    for (int i = 0; i < 8; ++i)
        #pragma unroll
        for (int j = 0; j < 4; ++j) acc[i][j] = 0ull;

    for (int kb = 0; kb < DIM_; kb += 32) {
        {
            const int r  = tid >> 3;
            const int kc = (tid & 7) * 4;
            #pragma unroll
            for (int it = 0; it < 4; ++it) {
                int m = r + it * 32;
                float4 v = *(const float4*)&A[(size_t)(m0 + m) * DIM_ + kb + kc];
                As[(kc + 0) * 132 + m] = v.x;
                As[(kc + 1) * 132 + m] = v.y;
                As[(kc + 2) * 132 + m] = v.z;
                As[(kc + 3) * 132 + m] = v.w;
            }
        }
        {
            const int k = tid >> 5;
            const int n = (tid & 31) * 4;
            #pragma unroll
            for (int it = 0; it < 4; ++it) {
                float4 v = *(const float4*)&W[(size_t)(kb + k + it * 8) * DIM_ + n0 + n];
                *(float4*)&Ws[(k + it * 8) * 132 + n] = v;
            }
        }
        __syncthreads();

        #pragma unroll
        for (int k = 0; k < 32; ++k) {
            float4 a0 = *(const float4*)&As[k * 132 + ty * 8];
            float4 a1 = *(const float4*)&As[k * 132 + ty * 8 + 4];
            ulonglong2 w0 = *(const ulonglong2*)&Ws[k * 132 + tx * 8];
            ulonglong2 w1 = *(const ulonglong2*)&Ws[k * 132 + tx * 8 + 4];
            u64x2 wv[4] = {w0.x, w0.y, w1.x, w1.y};
            float af[8] = {a0.x, a0.y, a0.z, a0.w, a1.x, a1.y, a1.z, a1.w};
            u64x2 ad[8];
            #pragma unroll
            for (int i = 0; i < 8; ++i) ad[i] = dup2(af[i]);
            #pragma unroll
            for (int i = 0; i < 8; ++i)
                #pragma unroll
                for (int j = 0; j < 4; ++j)
                    fma2(acc[i][j], ad[i], wv[j]);
        }
        __syncthreads();
    }

    float4 b0 = *(const float4*)&bias[n0 + tx * 8];
    float4 b1 = *(const float4*)&bias[n0 + tx * 8 + 4];
    float bf[8] = {b0.x, b0.y, b0.z, b0.w, b1.x, b1.y, b1.z, b1.w};
    #pragma unroll
    for (int i = 0; i < 8; ++i) {
        size_t row = (size_t)(m0 + ty * 8 + i) * DIM_ + n0 + tx * 8;
        float ov[8];
        #pragma unroll
        for (int j = 0; j < 4; ++j) {
            float2 e = unpk2(acc[i][j]);
            ov[2 * j]     = e.x + bf[2 * j];
            ov[2 * j + 1] = e.y + bf[2 * j + 1];
        }
        *(float4*)&C[row]     = make_float4(ov[0], ov[1], ov[2], ov[3]);
        *(float4*)&C[row + 4] = make_float4(ov[4], ov[5], ov[6], ov[7]);
    }
}

// ---------------------------------------------------------------------------
// Flash attention, f32x2 inner loops.
// Ks swizzle: word(d,k) = d*128 + (((k>>2) ^ (d&31)) << 2) + (k&3)
// ---------------------------------------------------------------------------
#define ATTN_SMEM_FLOATS (64 * 64 + 64 * 128 + 64 * 132)
#define ATTN_SMEM_BYTES  (ATTN_SMEM_FLOATS * 4)

__global__ __launch_bounds__(256, 2)
void attn_kernel(const float* __restrict__ Lp, const float* __restrict__ Qp,
                 float* __restrict__ Xp) {
    extern __shared__ float smem[];
    float* Qs = smem;                  // [64 d][64 q]
    float* Ks = smem + 64 * 64;        // swizzled [64 d][128 k]
    float* Ps = Ks + 64 * 128;         // [64 q][132]

    const int tid = threadIdx.x;
    const int tx  = tid & 15;
    const int ty  = tid >> 4;
    const int qb  = blockIdx.x;
    const int h   = blockIdx.y;
    const int b   = blockIdx.z;

    const float scale = 0.00552427172801990775f;  // 1/(8*sqrt(512))

    {
        const int r  = tid >> 4;
        const int d0 = (tid & 15) * 4;
        const float* qbase = Qp + ((size_t)b * LQ_ + (size_t)qb * 64) * DIM_ + h * DK_;
        #pragma unroll
        for (int it = 0; it < 4; ++it) {
            int row = r + it * 16;
            float4 v = *(const float4*)&qbase[(size_t)row * DIM_ + d0];
            Qs[(d0 + 0) * 64 + row] = v.x * scale;
            Qs[(d0 + 1) * 64 + row] = v.y * scale;
            Qs[(d0 + 2) * 64 + row] = v.z * scale;
            Qs[(d0 + 3) * 64 + row] = v.w * scale;
        }
    }

    // o2[i][dj]: packed over even/odd k partial sums (horizontal add at end)
    u64x2 o2[4][4];
    float m_[4], l_[4];
    #pragma unroll
    for (int i = 0; i < 4; ++i) {
        m_[i] = -1.0e30f; l_[i] = 0.f;
        #pragma unroll
        for (int j = 0; j < 4; ++j) o2[i][j] = 0ull;
    }

    const float* lbase = Lp + (size_t)b * LK_ * DIM_ + h * DK_;

    for (int kt = 0; kt < LK_ / 128; ++kt) {
        __syncthreads();

        {
            const int r  = tid >> 4;
            const int d0 = (tid & 15) * 4;
            #pragma unroll
            for (int it = 0; it < 8; ++it) {
                int row = r + it * 16;
                float4 v = *(const float4*)&lbase[(size_t)(kt * 128 + row) * DIM_ + d0];
                int kg = row >> 2, kc = row & 3;
                Ks[(d0 + 0) * 128 + ((kg ^ ((d0 + 0) & 31)) << 2) + kc] = v.x;
                Ks[(d0 + 1) * 128 + ((kg ^ ((d0 + 1) & 31)) << 2) + kc] = v.y;
                Ks[(d0 + 2) * 128 + ((kg ^ ((d0 + 2) & 31)) << 2) + kc] = v.z;
                Ks[(d0 + 3) * 128 + ((kg ^ ((d0 + 3) & 31)) << 2) + kc] = v.w;
            }
        }
        __syncthreads();

        // ---- S = QK^T, packed along k: s2[i][j] lanes = k (tx*8+2j, +2j+1)
        u64x2 s2[4][4];
        #pragma unroll
        for (int i = 0; i < 4; ++i)
            #pragma unroll
            for (int j = 0; j < 4; ++j) s2[i][j] = 0ull;

        #pragma unroll 8
        for (int d = 0; d < 64; ++d) {
            const int dx = d & 31;
            float4 qv = *(const float4*)&Qs[d * 64 + ty * 4];
            ulonglong2 k0 = *(const ulonglong2*)&Ks[d * 128 + (((2 * tx + 0) ^ dx) << 2)];
            ulonglong2 k1 = *(const ulonglong2*)&Ks[d * 128 + (((2 * tx + 1) ^ dx) << 2)];
            u64x2 kv[4] = {k0.x, k0.y, k1.x, k1.y};
            u64x2 qd[4] = {dup2(qv.x), dup2(qv.y), dup2(qv.z), dup2(qv.w)};
            #pragma unroll
            for (int i = 0; i < 4; ++i)
                #pragma unroll
                for (int j = 0; j < 4; ++j)
                    fma2(s2[i][j], qd[i], kv[j]);
        }

        // ---- online softmax ----
        #pragma unroll
        for (int i = 0; i < 4; ++i) {
            float s[8];
            #pragma unroll
            for (int j = 0; j < 4; ++j) {
                float2 e = unpk2(s2[i][j]);
                s[2 * j] = e.x; s[2 * j + 1] = e.y;
            }
            float rm = s[0];
            #pragma unroll
            for (int j = 1; j < 8; ++j) rm = fmaxf(rm, s[j]);
            rm = fmaxf(rm, __shfl_xor_sync(0xffffffffu, rm, 8));
            rm = fmaxf(rm, __shfl_xor_sync(0xffffffffu, rm, 4));
            rm = fmaxf(rm, __shfl_xor_sync(0xffffffffu, rm, 2));
            rm = fmaxf(rm, __shfl_xor_sync(0xffffffffu, rm, 1));
            float mn    = fmaxf(m_[i], rm);
            float alpha = __expf(m_[i] - mn);
            float p[8];
            float rs = 0.f;
            #pragma unroll
            for (int j = 0; j < 8; ++j) { p[j] = __expf(s[j] - mn); rs += p[j]; }
            rs += __shfl_xor_sync(0xffffffffu, rs, 8);
            rs += __shfl_xor_sync(0xffffffffu, rs, 4);
            rs += __shfl_xor_sync(0xffffffffu, rs, 2);
            rs += __shfl_xor_sync(0xffffffffu, rs, 1);
            l_[i] = l_[i] * alpha + rs;
            m_[i] = mn;
            u64x2 al = dup2(alpha);
            #pragma unroll
            for (int j = 0; j < 4; ++j) mul2(o2[i][j], al);
            *(float4*)&Ps[(ty * 4 + i) * 132 + tx * 8]     = make_float4(p[0], p[1], p[2], p[3]);
            *(float4*)&Ps[(ty * 4 + i) * 132 + tx * 8 + 4] = make_float4(p[4], p[5], p[6], p[7]);
        }
        __syncthreads();

        // ---- O += P V: packed k-reduction, both operands pre-packed ----
        int dgb[4], dgx[4];
        #pragma unroll
        for (int dj = 0; dj < 4; ++dj) {
            int d = tx * 4 + dj;
            dgb[dj] = d * 128;
            dgx[dj] = d & 31;
        }
        #pragma unroll 4
        for (int kk4 = 0; kk4 < 32; ++kk4) {
            u64x2 vv[4][2];
            #pragma unroll
            for (int dj = 0; dj < 4; ++dj) {
                ulonglong2 v = *(const ulonglong2*)&Ks[dgb[dj] + ((kk4 ^ dgx[dj]) << 2)];
                vv[dj][0] = v.x; vv[dj][1] = v.y;
            }
            #pragma unroll
            for (int i = 0; i < 4; ++i) {
                ulonglong2 pp = *(const ulonglong2*)&Ps[(ty * 4 + i) * 132 + (kk4 << 2)];
                #pragma unroll
                for (int dj = 0; dj < 4; ++dj) {
                    fma2(o2[i][dj], pp.x, vv[dj][0]);
                    fma2(o2[i][dj], pp.y, vv[dj][1]);
                }
            }
        }
    }

    // ---- epilogue: horizontal add, normalize, store ----
    #pragma unroll
    for (int i = 0; i < 4; ++i) {
        float inv = 1.f / l_[i];
        size_t row = (size_t)b * LQ_ + (size_t)qb * 64 + ty * 4 + i;
        float ov[4];
        #pragma unroll
        for (int dj = 0; dj < 4; ++dj) {
            float2 e = unpk2(o2[i][dj]);
            ov[dj] = (e.x + e.y) * inv;
        }
        *(float4*)&Xp[row * DIM_ + h * DK_ + tx * 4] =
            make_float4(ov[0], ov[1], ov[2], ov[3]);
    }
}

// ---------------------------------------------------------------------------
extern "C" void kernel_launch(void* const* d_in, const int* in_sizes, int n_in,
                              void* d_out, int out_size) {
    const float* L  = (const float*)d_in[0];
    const float* G  = (const float*)d_in[1];
    const float* Wq = (const float*)d_in[2];
    const float* bq = (const float*)d_in[3];
    const float* Wo = (const float*)d_in[4];
    const float* bo = (const float*)d_in[5];
    float* out = (float*)d_out;

    float *qbuf, *xbuf;
    cudaGetSymbolAddress((void**)&qbuf, g_q);
    cudaGetSymbolAddress((void**)&xbuf, g_x);

    cudaFuncSetAttribute(attn_kernel,
                         cudaFuncAttributeMaxDynamicSharedMemorySize,
                         ATTN_SMEM_BYTES);

    dim3 gProj(DIM_ / 128, (B_ * LQ_) / 128);
    dim3 gAttn(LQ_ / 64, H_, B_);

    gemm_bias_kernel<<<gProj, 256>>>(G, Wq, bq, qbuf);
    attn_kernel<<<gAttn, 256, ATTN_SMEM_BYTES>>>(L, qbuf, xbuf);
    gemm_bias_kernel<<<gProj, 256>>>(xbuf, Wo, bo, out);
}

// round 4
// speedup vs baseline: 2.4322x; 2.4263x over previous
#include <cuda_runtime.h>
#include <cuda_bf16.h>
#include <stdint.h>

#define B_   16
#define LK_  2048
#define LQ_  256
#define DIM_ 512
#define H_   8
#define DK_  64

typedef unsigned long long u64x2;

__device__ __forceinline__ u64x2 dup2(float v) {
    u64x2 r; asm("mov.b64 %0, {%1, %1};" : "=l"(r) : "f"(v)); return r;
}
__device__ __forceinline__ float2 unpk2(u64x2 v) {
    float2 f; asm("mov.b64 {%0, %1}, %2;" : "=f"(f.x), "=f"(f.y) : "l"(v)); return f;
}
__device__ __forceinline__ void fma2(u64x2& d, u64x2 a, u64x2 b) {
    asm("fma.rn.f32x2 %0, %1, %2, %0;" : "+l"(d) : "l"(a), "l"(b));
}

__device__ __forceinline__ uint32_t pack_bf16(float x, float y) {
    __nv_bfloat162 h = __float22bfloat162_rn(make_float2(x, y));
    return *(uint32_t*)&h;
}
__device__ __forceinline__ void pack_split(float x, float y, uint32_t& hi, uint32_t& lo) {
    __nv_bfloat162 h = __float22bfloat162_rn(make_float2(x, y));
    float2 hf = __bfloat1622float2(h);
    __nv_bfloat162 l = __float22bfloat162_rn(make_float2(x - hf.x, y - hf.y));
    hi = *(uint32_t*)&h;
    lo = *(uint32_t*)&l;
}

__device__ __forceinline__ void ldsm4(uint32_t* r, uint32_t addr) {
    asm volatile("ldmatrix.sync.aligned.m8n8.x4.shared.b16 {%0,%1,%2,%3}, [%4];"
        : "=r"(r[0]), "=r"(r[1]), "=r"(r[2]), "=r"(r[3]) : "r"(addr));
}
__device__ __forceinline__ void ldsm4t(uint32_t* r, uint32_t addr) {
    asm volatile("ldmatrix.sync.aligned.m8n8.x4.trans.shared.b16 {%0,%1,%2,%3}, [%4];"
        : "=r"(r[0]), "=r"(r[1]), "=r"(r[2]), "=r"(r[3]) : "r"(addr));
}
__device__ __forceinline__ void mma16816(float* c, const uint32_t* a,
                                         uint32_t b0, uint32_t b1) {
    asm volatile("mma.sync.aligned.m16n8k16.row.col.f32.bf16.bf16.f32 "
        "{%0,%1,%2,%3}, {%4,%5,%6,%7}, {%8,%9}, {%0,%1,%2,%3};"
        : "+f"(c[0]), "+f"(c[1]), "+f"(c[2]), "+f"(c[3])
        : "r"(a[0]), "r"(a[1]), "r"(a[2]), "r"(a[3]), "r"(b0), "r"(b1));
}

// scratch (allocation-free rule: __device__ globals)
__device__ float g_q[B_ * LQ_ * DIM_];
__device__ float g_x[B_ * LQ_ * DIM_];

// ---------------------------------------------------------------------------
// GEMM: C[M,512] = A[M,512] @ W + bias.  BM=64, BN=128, BK=32, 256 thr, f32x2
// ---------------------------------------------------------------------------
__global__ __launch_bounds__(256, 2)
void gemm_bias_kernel(const float* __restrict__ A, const float* __restrict__ W,
                      const float* __restrict__ bias, float* __restrict__ C) {
    __shared__ float As[32 * 68];
    __shared__ float Ws[32 * 132];

    const int tid = threadIdx.x;
    const int tx  = tid & 15;
    const int ty  = tid >> 4;
    const int n0  = blockIdx.x * 128;
    const int m0  = blockIdx.y * 64;

    u64x2 acc[4][4];
    #pragma unroll
    for (int i = 0; i < 4; ++i)
        #pragma unroll
        for (int j = 0; j < 4; ++j) acc[i][j] = 0ull;

    for (int kb = 0; kb < DIM_; kb += 32) {
        {
            const int r  = tid >> 3;
            const int kc = (tid & 7) * 4;
            #pragma unroll
            for (int it = 0; it < 2; ++it) {
                int m = r + it * 32;
                float4 v = *(const float4*)&A[(size_t)(m0 + m) * DIM_ + kb + kc];
                As[(kc + 0) * 68 + m] = v.x;
                As[(kc + 1) * 68 + m] = v.y;
                As[(kc + 2) * 68 + m] = v.z;
                As[(kc + 3) * 68 + m] = v.w;
            }
        }
        {
            const int k = tid >> 5;
            const int n = (tid & 31) * 4;
            #pragma unroll
            for (int it = 0; it < 4; ++it) {
                float4 v = *(const float4*)&W[(size_t)(kb + k + it * 8) * DIM_ + n0 + n];
                *(float4*)&Ws[(k + it * 8) * 132 + n] = v;
            }
        }
        __syncthreads();

        #pragma unroll
        for (int k = 0; k < 32; ++k) {
            float4 a = *(const float4*)&As[k * 68 + ty * 4];
            ulonglong2 w0 = *(const ulonglong2*)&Ws[k * 132 + tx * 8];
            ulonglong2 w1 = *(const ulonglong2*)&Ws[k * 132 + tx * 8 + 4];
            u64x2 wv[4] = {w0.x, w0.y, w1.x, w1.y};
            float af[4] = {a.x, a.y, a.z, a.w};
            #pragma unroll
            for (int i = 0; i < 4; ++i) {
                u64x2 ad = dup2(af[i]);
                #pragma unroll
                for (int j = 0; j < 4; ++j) fma2(acc[i][j], ad, wv[j]);
            }
        }
        __syncthreads();
    }

    float4 b0 = *(const float4*)&bias[n0 + tx * 8];
    float4 b1 = *(const float4*)&bias[n0 + tx * 8 + 4];
    float bf[8] = {b0.x, b0.y, b0.z, b0.w, b1.x, b1.y, b1.z, b1.w};
    #pragma unroll
    for (int i = 0; i < 4; ++i) {
        size_t row = (size_t)(m0 + ty * 4 + i) * DIM_ + n0 + tx * 8;
        float ov[8];
        #pragma unroll
        for (int j = 0; j < 4; ++j) {
            float2 e = unpk2(acc[i][j]);
            ov[2 * j]     = e.x + bf[2 * j];
            ov[2 * j + 1] = e.y + bf[2 * j + 1];
        }
        *(float4*)&C[row]     = make_float4(ov[0], ov[1], ov[2], ov[3]);
        *(float4*)&C[row + 4] = make_float4(ov[4], ov[5], ov[6], ov[7]);
    }
}

// ---------------------------------------------------------------------------
// FA2 on warp mma.sync (bf16). CTA = (qb, h, b): Q[128,64]; 16 K-tiles of 128.
// S: single bf16 (logits tiny). PV: 3-term hi/lo split.
// K smem [token][d] bf16, XOR-swizzled; serves as K (ldmatrix) and V (.trans).
// ---------------------------------------------------------------------------
__global__ __launch_bounds__(256, 1)
void attn_mma_kernel(const float* __restrict__ Lp, const float* __restrict__ Qp,
                     float* __restrict__ Xp) {
    __shared__ __nv_bfloat16 KsH[128 * 64];
    __shared__ __nv_bfloat16 KsL[128 * 64];

    const int tid  = threadIdx.x;
    const int wid  = tid >> 5;
    const int lane = tid & 31;
    const int g = lane >> 2, t = lane & 3;
    const int qb = blockIdx.x, h = blockIdx.y, b = blockIdx.z;
    const float scale = 0.00552427172801990775f;   // 1/(8*sqrt(512))

    const uint32_t khb = (uint32_t)__cvta_generic_to_shared(KsH);
    const uint32_t klb = (uint32_t)__cvta_generic_to_shared(KsL);

    // ---- Q A-fragments (bf16, pre-scaled), resident all kernel ----
    uint32_t qa[4][4];
    {
        const float* qbase =
            Qp + ((size_t)b * LQ_ + (size_t)qb * 128 + wid * 16) * DIM_ + h * DK_;
        #pragma unroll
        for (int s = 0; s < 4; ++s) {
            int d0 = 16 * s + 2 * t;
            float2 v0 = *(const float2*)&qbase[(size_t)g * DIM_ + d0];
            float2 v1 = *(const float2*)&qbase[(size_t)(g + 8) * DIM_ + d0];
            float2 v2 = *(const float2*)&qbase[(size_t)g * DIM_ + d0 + 8];
            float2 v3 = *(const float2*)&qbase[(size_t)(g + 8) * DIM_ + d0 + 8];
            qa[s][0] = pack_bf16(v0.x * scale, v0.y * scale);
            qa[s][1] = pack_bf16(v1.x * scale, v1.y * scale);
            qa[s][2] = pack_bf16(v2.x * scale, v2.y * scale);
            qa[s][3] = pack_bf16(v3.x * scale, v3.y * scale);
        }
    }

    // ---- K tile loader mapping + prefetch of tile 0 ----
    const int lr0 = tid >> 4;          // 0..15
    const int ld4 = (tid & 15) * 4;    // 0..60
    const float* lbase = Lp + (size_t)b * LK_ * DIM_ + h * DK_;

    float4 pf[8];
    #pragma unroll
    for (int it = 0; it < 8; ++it)
        pf[it] = *(const float4*)&lbase[(size_t)(lr0 + it * 16) * DIM_ + ld4];

    float oacc[8][4];
    #pragma unroll
    for (int i = 0; i < 8; ++i)
        #pragma unroll
        for (int j = 0; j < 4; ++j) oacc[i][j] = 0.f;
    float lacc0 = 0.f, lacc1 = 0.f;

    // ldmatrix lane-address components (kt-invariant)
    const uint32_t sXor  = (uint32_t)(lane & 7) << 4;          // swizzle XOR
    const uint32_t sRow  = (uint32_t)(lane & 7) * 128;
    const uint32_t sOff0 = sRow + ((((uint32_t)(lane >> 3)) * 16 +  0) ^ sXor);
    const uint32_t sOff1 = sRow + ((((uint32_t)(lane >> 3)) * 16 + 64) ^ sXor);
    const uint32_t vRow  = (uint32_t)(lane & 15) * 128;
    const uint32_t vD    = (uint32_t)(lane >> 4) * 16;

    for (int kt = 0; kt < 16; ++kt) {
        __syncthreads();   // previous tile fully consumed
        #pragma unroll
        for (int it = 0; it < 8; ++it) {
            int r = lr0 + it * 16;
            uint32_t hx, lx, hy, ly;
            pack_split(pf[it].x, pf[it].y, hx, lx);
            pack_split(pf[it].z, pf[it].w, hy, ly);
            uint32_t off = (uint32_t)(r * 128 + ld4 * 2);
            off = off ^ ((off >> 3) & 0x70);
            *(uint2*)((char*)KsH + off) = make_uint2(hx, hy);
            *(uint2*)((char*)KsL + off) = make_uint2(lx, ly);
        }
        __syncthreads();

        if (kt < 15) {   // prefetch next tile behind compute
            #pragma unroll
            for (int it = 0; it < 8; ++it)
                pf[it] = *(const float4*)
                    &lbase[(size_t)((kt + 1) * 128 + lr0 + it * 16) * DIM_ + ld4];
        }

        // ---- S = Q K^T (single bf16 term) ----
        float sacc[16][4];
        #pragma unroll
        for (int nf = 0; nf < 16; ++nf) {
            sacc[nf][0] = 0.f; sacc[nf][1] = 0.f;
            sacc[nf][2] = 0.f; sacc[nf][3] = 0.f;
        }
        #pragma unroll
        for (int nf = 0; nf < 16; ++nf) {
            uint32_t bfr[8];
            ldsm4(bfr + 0, khb + (uint32_t)(nf * 1024) + sOff0);
            ldsm4(bfr + 4, khb + (uint32_t)(nf * 1024) + sOff1);
            #pragma unroll
            for (int s = 0; s < 4; ++s)
                mma16816(sacc[nf], qa[s], bfr[2 * s], bfr[2 * s + 1]);
        }

        // ---- softmax numerators (no max-subtract: |logit| <= ~0.5) ----
        #pragma unroll
        for (int nf = 0; nf < 16; ++nf) {
            float p0 = __expf(sacc[nf][0]);
            float p1 = __expf(sacc[nf][1]);
            float p2 = __expf(sacc[nf][2]);
            float p3 = __expf(sacc[nf][3]);
            lacc0 += p0 + p1;
            lacc1 += p2 + p3;
            sacc[nf][0] = p0; sacc[nf][1] = p1;
            sacc[nf][2] = p2; sacc[nf][3] = p3;
        }

        // ---- O += P V (P from S-frags; 3-term hi/lo) ----
        #pragma unroll
        for (int u = 0; u < 8; ++u) {
            uint32_t pah[4], pal[4];
            pack_split(sacc[2 * u][0],     sacc[2 * u][1],     pah[0], pal[0]);
            pack_split(sacc[2 * u][2],     sacc[2 * u][3],     pah[1], pal[1]);
            pack_split(sacc[2 * u + 1][0], sacc[2 * u + 1][1], pah[2], pal[2]);
            pack_split(sacc[2 * u + 1][2], sacc[2 * u + 1][3], pah[3], pal[3]);
            #pragma unroll
            for (int dfp = 0; dfp < 4; ++dfp) {
                uint32_t voff = vRow + (uint32_t)(u * 2048)
                              + (((uint32_t)(dfp * 32) + vD) ^ sXor);
                uint32_t vh[4], vl[4];
                ldsm4t(vh, khb + voff);
                ldsm4t(vl, klb + voff);
                mma16816(oacc[2 * dfp],     pah, vh[0], vh[1]);
                mma16816(oacc[2 * dfp],     pah, vl[0], vl[1]);
                mma16816(oacc[2 * dfp],     pal, vh[0], vh[1]);
                mma16816(oacc[2 * dfp + 1], pah, vh[2], vh[3]);
                mma16816(oacc[2 * dfp + 1], pah, vl[2], vl[3]);
                mma16816(oacc[2 * dfp + 1], pal, vh[2], vh[3]);
            }
        }
    }

    // ---- epilogue: reduce l over quad, normalize, store ----
    lacc0 += __shfl_xor_sync(0xffffffffu, lacc0, 1);
    lacc0 += __shfl_xor_sync(0xffffffffu, lacc0, 2);
    lacc1 += __shfl_xor_sync(0xffffffffu, lacc1, 1);
    lacc1 += __shfl_xor_sync(0xffffffffu, lacc1, 2);
    float inv0 = 1.f / lacc0, inv1 = 1.f / lacc1;

    float* xr = Xp + ((size_t)b * LQ_ + (size_t)qb * 128 + wid * 16) * DIM_ + h * DK_;
    #pragma unroll
    for (int df = 0; df < 8; ++df) {
        int c = df * 8 + 2 * t;
        *(float2*)&xr[(size_t)g * DIM_ + c] =
            make_float2(oacc[df][0] * inv0, oacc[df][1] * inv0);
        *(float2*)&xr[(size_t)(g + 8) * DIM_ + c] =
            make_float2(oacc[df][2] * inv1, oacc[df][3] * inv1);
    }
}

// ---------------------------------------------------------------------------
extern "C" void kernel_launch(void* const* d_in, const int* in_sizes, int n_in,
                              void* d_out, int out_size) {
    const float* L  = (const float*)d_in[0];
    const float* G  = (const float*)d_in[1];
    const float* Wq = (const float*)d_in[2];
    const float* bq = (const float*)d_in[3];
    const float* Wo = (const float*)d_in[4];
    const float* bo = (const float*)d_in[5];
    float* out = (float*)d_out;

    float *qbuf, *xbuf;
    cudaGetSymbolAddress((void**)&qbuf, g_q);
    cudaGetSymbolAddress((void**)&xbuf, g_x);

    dim3 gProj(DIM_ / 128, (B_ * LQ_) / 64);    // (4, 64) = 256 CTAs
    dim3 gAttn(LQ_ / 128, H_, B_);              // (2, 8, 16) = 256 CTAs

    gemm_bias_kernel<<<gProj, 256>>>(G, Wq, bq, qbuf);
    attn_mma_kernel<<<gAttn, 256>>>(L, qbuf, xbuf);
    gemm_bias_kernel<<<gProj, 256>>>(xbuf, Wo, bo, out);
}

// round 5
// speedup vs baseline: 7.1201x; 2.9274x over previous
#include <cuda_runtime.h>
#include <cuda_bf16.h>
#include <stdint.h>

#define B_   16
#define LK_  2048
#define LQ_  256
#define DIM_ 512
#define H_   8
#define DK_  64
#define M_   (B_ * LQ_)     // 4096

// ---------------- helpers ----------------
__device__ __forceinline__ uint32_t pack_bf16(float x, float y) {
    __nv_bfloat162 h = __float22bfloat162_rn(make_float2(x, y));
    return *(uint32_t*)&h;
}
__device__ __forceinline__ void pack_split(float x, float y, uint32_t& hi, uint32_t& lo) {
    __nv_bfloat162 h = __float22bfloat162_rn(make_float2(x, y));
    float2 hf = __bfloat1622float2(h);
    __nv_bfloat162 l = __float22bfloat162_rn(make_float2(x - hf.x, y - hf.y));
    hi = *(uint32_t*)&h;
    lo = *(uint32_t*)&l;
}
__device__ __forceinline__ void ldsm4(uint32_t* r, uint32_t addr) {
    asm volatile("ldmatrix.sync.aligned.m8n8.x4.shared.b16 {%0,%1,%2,%3}, [%4];"
        : "=r"(r[0]), "=r"(r[1]), "=r"(r[2]), "=r"(r[3]) : "r"(addr));
}
__device__ __forceinline__ void ldsm4t(uint32_t* r, uint32_t addr) {
    asm volatile("ldmatrix.sync.aligned.m8n8.x4.trans.shared.b16 {%0,%1,%2,%3}, [%4];"
        : "=r"(r[0]), "=r"(r[1]), "=r"(r[2]), "=r"(r[3]) : "r"(addr));
}
__device__ __forceinline__ void mma16816(float* c, const uint32_t* a,
                                         uint32_t b0, uint32_t b1) {
    asm volatile("mma.sync.aligned.m16n8k16.row.col.f32.bf16.bf16.f32 "
        "{%0,%1,%2,%3}, {%4,%5,%6,%7}, {%8,%9}, {%0,%1,%2,%3};"
        : "+f"(c[0]), "+f"(c[1]), "+f"(c[2]), "+f"(c[3])
        : "r"(a[0]), "r"(a[1]), "r"(a[2]), "r"(a[3]), "r"(b0), "r"(b1));
}
__device__ __forceinline__ void cp16(uint32_t dst, const void* src) {
    asm volatile("cp.async.cg.shared.global [%0], [%1], 16;" :: "r"(dst), "l"(src));
}

// ---------------- scratch (__device__ globals, allocation-free) ----------------
__device__ float         g_q  [M_ * DIM_];
__device__ __nv_bfloat16 g_gh [M_ * DIM_], g_gl [M_ * DIM_];
__device__ __nv_bfloat16 g_xh [M_ * DIM_], g_xl [M_ * DIM_];
__device__ __nv_bfloat16 g_wqh[DIM_ * DIM_], g_wql[DIM_ * DIM_];
__device__ __nv_bfloat16 g_woh[DIM_ * DIM_], g_wol[DIM_ * DIM_];

// ---------------------------------------------------------------------------
// Prep: split G, Wq, Wo into bf16 hi/lo (2 elems per thread)
// ---------------------------------------------------------------------------
#define NG (M_ * DIM_ / 2)
#define NW (DIM_ * DIM_ / 2)

__global__ void prep_kernel(const float* __restrict__ G,
                            const float* __restrict__ Wq,
                            const float* __restrict__ Wo) {
    int i = blockIdx.x * blockDim.x + threadIdx.x;
    uint32_t h, l;
    if (i < NG) {
        float2 v = ((const float2*)G)[i];
        pack_split(v.x, v.y, h, l);
        ((uint32_t*)g_gh)[i] = h; ((uint32_t*)g_gl)[i] = l;
    } else if (i < NG + NW) {
        int j = i - NG;
        float2 v = ((const float2*)Wq)[j];
        pack_split(v.x, v.y, h, l);
        ((uint32_t*)g_wqh)[j] = h; ((uint32_t*)g_wql)[j] = l;
    } else if (i < NG + 2 * NW) {
        int j = i - NG - NW;
        float2 v = ((const float2*)Wo)[j];
        pack_split(v.x, v.y, h, l);
        ((uint32_t*)g_woh)[j] = h; ((uint32_t*)g_wol)[j] = l;
    }
}

// ---------------------------------------------------------------------------
// GEMM on mma.sync: C[4096,512] = A @ W + bias, bf16 hi/lo 3-term.
// BM=BN=128, BK=64, 8 warps (warp = m16 x n128). cp.async double buffer.
// A smem [m][k] 128B rows (ldsm4); W smem [k][n] 256B rows (ldsm4t).
// ---------------------------------------------------------------------------
#define GS_STAGE 65536
#define GS_A_L   16384
#define GS_W_H   32768
#define GEMM_SMEM (2 * GS_STAGE)   // 128 KB

__global__ __launch_bounds__(256, 1)
void gemm_mma_kernel(const __nv_bfloat16* __restrict__ Ah,
                     const __nv_bfloat16* __restrict__ Al,
                     const __nv_bfloat16* __restrict__ Wh,
                     const __nv_bfloat16* __restrict__ Wl,
                     const float* __restrict__ bias,
                     float* __restrict__ C) {
    extern __shared__ char sm[];
    const uint32_t sb = (uint32_t)__cvta_generic_to_shared(sm);
    const int tid = threadIdx.x, wid = tid >> 5, lane = tid & 31;
    const int g = lane >> 2, t = lane & 3;
    const int n0 = blockIdx.x * 128, m0 = blockIdx.y * 128;

    // cp.async granule mapping (4 granules per array per thread)
    int alin[4], wlin[4];
    #pragma unroll
    for (int i = 0; i < 4; ++i) { alin[i] = tid + i * 256; wlin[i] = tid + i * 256; }

    auto issue = [&](int kb, int s) {
        uint32_t base = sb + (uint32_t)s * GS_STAGE;
        #pragma unroll
        for (int i = 0; i < 4; ++i) {
            int ar = alin[i] >> 3, ac = alin[i] & 7;
            uint32_t ad = base + (uint32_t)(((ar * 128 + ac * 16) ^ ((ar & 7) << 4)));
            size_t asrc = (size_t)(m0 + ar) * DIM_ + kb * 64 + ac * 8;
            cp16(ad,           Ah + asrc);
            cp16(ad + GS_A_L,  Al + asrc);
            int wr = wlin[i] >> 4, wc = wlin[i] & 15;
            uint32_t wd = base + GS_W_H +
                          (uint32_t)(((wr * 256 + wc * 16) ^ ((wr & 7) << 4)));
            size_t wsrc = (size_t)(kb * 64 + wr) * DIM_ + n0 + wc * 8;
            cp16(wd,           Wh + wsrc);
            cp16(wd + 16384,   Wl + wsrc);
        }
        asm volatile("cp.async.commit_group;");
    };

    float acc[16][4];
    #pragma unroll
    for (int j = 0; j < 16; ++j) {
        acc[j][0] = 0.f; acc[j][1] = 0.f; acc[j][2] = 0.f; acc[j][3] = 0.f;
    }

    const uint32_t xr   = (uint32_t)(lane & 7) << 4;
    const uint32_t cH   = (uint32_t)(lane >> 4) * 16;
    const uint32_t aRow = (uint32_t)((wid * 16 + (lane & 15)) * 128);
    const uint32_t wRow = (uint32_t)((lane & 15) * 256);

    issue(0, 0);
    for (int kb = 0; kb < 8; ++kb) {
        if (kb < 7) {
            issue(kb + 1, (kb + 1) & 1);
            asm volatile("cp.async.wait_group 1;");
        } else {
            asm volatile("cp.async.wait_group 0;");
        }
        __syncthreads();

        uint32_t base = sb + (uint32_t)(kb & 1) * GS_STAGE;
        uint32_t ahf[4][4], alf[4][4];
        #pragma unroll
        for (int s = 0; s < 4; ++s) {
            uint32_t ad = base + aRow + (((uint32_t)(s * 32) + cH) ^ xr);
            ldsm4(ahf[s], ad);
            ldsm4(alf[s], ad + GS_A_L);
        }
        #pragma unroll
        for (int s = 0; s < 4; ++s) {
            #pragma unroll
            for (int nf = 0; nf < 8; ++nf) {
                uint32_t wa = base + GS_W_H + (uint32_t)(s * 4096) + wRow +
                              (((uint32_t)(nf * 32) + cH) ^ xr);
                uint32_t wh[4], wl[4];
                ldsm4t(wh, wa);
                ldsm4t(wl, wa + 16384);
                mma16816(acc[2 * nf],     ahf[s], wh[0], wh[1]);
                mma16816(acc[2 * nf + 1], ahf[s], wh[2], wh[3]);
                mma16816(acc[2 * nf],     ahf[s], wl[0], wl[1]);
                mma16816(acc[2 * nf + 1], ahf[s], wl[2], wl[3]);
                mma16816(acc[2 * nf],     alf[s], wh[0], wh[1]);
                mma16816(acc[2 * nf + 1], alf[s], wh[2], wh[3]);
            }
        }
        __syncthreads();
    }

    // epilogue: + bias, fp32 out
    const int r0 = m0 + wid * 16 + g;
    #pragma unroll
    for (int j = 0; j < 16; ++j) {
        int c = n0 + j * 8 + 2 * t;
        float2 bv = *(const float2*)&bias[c];
        *(float2*)&C[(size_t)r0 * DIM_ + c] =
            make_float2(acc[j][0] + bv.x, acc[j][1] + bv.y);
        *(float2*)&C[(size_t)(r0 + 8) * DIM_ + c] =
            make_float2(acc[j][2] + bv.x, acc[j][3] + bv.y);
    }
}

// ---------------------------------------------------------------------------
// FA2 on warp mma.sync (bf16), as validated in R4; epilogue now emits bf16
// hi/lo directly for the output projection.
// ---------------------------------------------------------------------------
__global__ __launch_bounds__(256, 1)
void attn_mma_kernel(const float* __restrict__ Lp, const float* __restrict__ Qp,
                     __nv_bfloat16* __restrict__ Xh, __nv_bfloat16* __restrict__ Xl) {
    __shared__ __nv_bfloat16 KsH[128 * 64];
    __shared__ __nv_bfloat16 KsL[128 * 64];

    const int tid  = threadIdx.x;
    const int wid  = tid >> 5;
    const int lane = tid & 31;
    const int g = lane >> 2, t = lane & 3;
    const int qb = blockIdx.x, h = blockIdx.y, b = blockIdx.z;
    const float scale = 0.00552427172801990775f;   // 1/(8*sqrt(512))

    const uint32_t khb = (uint32_t)__cvta_generic_to_shared(KsH);
    const uint32_t klb = (uint32_t)__cvta_generic_to_shared(KsL);

    uint32_t qa[4][4];
    {
        const float* qbase =
            Qp + ((size_t)b * LQ_ + (size_t)qb * 128 + wid * 16) * DIM_ + h * DK_;
        #pragma unroll
        for (int s = 0; s < 4; ++s) {
            int d0 = 16 * s + 2 * t;
            float2 v0 = *(const float2*)&qbase[(size_t)g * DIM_ + d0];
            float2 v1 = *(const float2*)&qbase[(size_t)(g + 8) * DIM_ + d0];
            float2 v2 = *(const float2*)&qbase[(size_t)g * DIM_ + d0 + 8];
            float2 v3 = *(const float2*)&qbase[(size_t)(g + 8) * DIM_ + d0 + 8];
            qa[s][0] = pack_bf16(v0.x * scale, v0.y * scale);
            qa[s][1] = pack_bf16(v1.x * scale, v1.y * scale);
            qa[s][2] = pack_bf16(v2.x * scale, v2.y * scale);
            qa[s][3] = pack_bf16(v3.x * scale, v3.y * scale);
        }
    }

    const int lr0 = tid >> 4;
    const int ld4 = (tid & 15) * 4;
    const float* lbase = Lp + (size_t)b * LK_ * DIM_ + h * DK_;

    float4 pf[8];
    #pragma unroll
    for (int it = 0; it < 8; ++it)
        pf[it] = *(const float4*)&lbase[(size_t)(lr0 + it * 16) * DIM_ + ld4];

    float oacc[8][4];
    #pragma unroll
    for (int i = 0; i < 8; ++i)
        #pragma unroll
        for (int j = 0; j < 4; ++j) oacc[i][j] = 0.f;
    float lacc0 = 0.f, lacc1 = 0.f;

    const uint32_t sXor  = (uint32_t)(lane & 7) << 4;
    const uint32_t sRow  = (uint32_t)(lane & 7) * 128;
    const uint32_t sOff0 = sRow + ((((uint32_t)(lane >> 3)) * 16 +  0) ^ sXor);
    const uint32_t sOff1 = sRow + ((((uint32_t)(lane >> 3)) * 16 + 64) ^ sXor);
    const uint32_t vRow  = (uint32_t)(lane & 15) * 128;
    const uint32_t vD    = (uint32_t)(lane >> 4) * 16;

    for (int kt = 0; kt < 16; ++kt) {
        __syncthreads();
        #pragma unroll
        for (int it = 0; it < 8; ++it) {
            int r = lr0 + it * 16;
            uint32_t hx, lx, hy, ly;
            pack_split(pf[it].x, pf[it].y, hx, lx);
            pack_split(pf[it].z, pf[it].w, hy, ly);
            uint32_t off = (uint32_t)(r * 128 + ld4 * 2);
            off = off ^ ((off >> 3) & 0x70);
            *(uint2*)((char*)KsH + off) = make_uint2(hx, hy);
            *(uint2*)((char*)KsL + off) = make_uint2(lx, ly);
        }
        __syncthreads();

        if (kt < 15) {
            #pragma unroll
            for (int it = 0; it < 8; ++it)
                pf[it] = *(const float4*)
                    &lbase[(size_t)((kt + 1) * 128 + lr0 + it * 16) * DIM_ + ld4];
        }

        float sacc[16][4];
        #pragma unroll
        for (int nf = 0; nf < 16; ++nf) {
            sacc[nf][0] = 0.f; sacc[nf][1] = 0.f;
            sacc[nf][2] = 0.f; sacc[nf][3] = 0.f;
        }
        #pragma unroll
        for (int nf = 0; nf < 16; ++nf) {
            uint32_t bfr[8];
            ldsm4(bfr + 0, khb + (uint32_t)(nf * 1024) + sOff0);
            ldsm4(bfr + 4, khb + (uint32_t)(nf * 1024) + sOff1);
            #pragma unroll
            for (int s = 0; s < 4; ++s)
                mma16816(sacc[nf], qa[s], bfr[2 * s], bfr[2 * s + 1]);
        }

        #pragma unroll
        for (int nf = 0; nf < 16; ++nf) {
            float p0 = __expf(sacc[nf][0]);
            float p1 = __expf(sacc[nf][1]);
            float p2 = __expf(sacc[nf][2]);
            float p3 = __expf(sacc[nf][3]);
            lacc0 += p0 + p1;
            lacc1 += p2 + p3;
            sacc[nf][0] = p0; sacc[nf][1] = p1;
            sacc[nf][2] = p2; sacc[nf][3] = p3;
        }

        #pragma unroll
        for (int u = 0; u < 8; ++u) {
            uint32_t pah[4], pal[4];
            pack_split(sacc[2 * u][0],     sacc[2 * u][1],     pah[0], pal[0]);
            pack_split(sacc[2 * u][2],     sacc[2 * u][3],     pah[1], pal[1]);
            pack_split(sacc[2 * u + 1][0], sacc[2 * u + 1][1], pah[2], pal[2]);
            pack_split(sacc[2 * u + 1][2], sacc[2 * u + 1][3], pah[3], pal[3]);
            #pragma unroll
            for (int dfp = 0; dfp < 4; ++dfp) {
                uint32_t voff = vRow + (uint32_t)(u * 2048)
                              + (((uint32_t)(dfp * 32) + vD) ^ sXor);
                uint32_t vh[4], vl[4];
                ldsm4t(vh, khb + voff);
                ldsm4t(vl, klb + voff);
                mma16816(oacc[2 * dfp],     pah, vh[0], vh[1]);
                mma16816(oacc[2 * dfp + 1], pah, vh[2], vh[3]);
                mma16816(oacc[2 * dfp],     pah, vl[0], vl[1]);
                mma16816(oacc[2 * dfp + 1], pah, vl[2], vl[3]);
                mma16816(oacc[2 * dfp],     pal, vh[0], vh[1]);
                mma16816(oacc[2 * dfp + 1], pal, vh[2], vh[3]);
            }
        }
    }

    lacc0 += __shfl_xor_sync(0xffffffffu, lacc0, 1);
    lacc0 += __shfl_xor_sync(0xffffffffu, lacc0, 2);
    lacc1 += __shfl_xor_sync(0xffffffffu, lacc1, 1);
    lacc1 += __shfl_xor_sync(0xffffffffu, lacc1, 2);
    float inv0 = 1.f / lacc0, inv1 = 1.f / lacc1;

    size_t r0 = ((size_t)b * LQ_ + (size_t)qb * 128 + wid * 16 + g) * DIM_ + h * DK_;
    size_t r1 = r0 + 8 * DIM_;
    #pragma unroll
    for (int df = 0; df < 8; ++df) {
        int c = df * 8 + 2 * t;
        uint32_t h0, l0, h1, l1;
        pack_split(oacc[df][0] * inv0, oacc[df][1] * inv0, h0, l0);
        pack_split(oacc[df][2] * inv1, oacc[df][3] * inv1, h1, l1);
        *(uint32_t*)((char*)Xh + (r0 + c) * 2) = h0;
        *(uint32_t*)((char*)Xl + (r0 + c) * 2) = l0;
        *(uint32_t*)((char*)Xh + (r1 + c) * 2) = h1;
        *(uint32_t*)((char*)Xl + (r1 + c) * 2) = l1;
    }
}

// ---------------------------------------------------------------------------
extern "C" void kernel_launch(void* const* d_in, const int* in_sizes, int n_in,
                              void* d_out, int out_size) {
    const float* L  = (const float*)d_in[0];
    const float* G  = (const float*)d_in[1];
    const float* Wq = (const float*)d_in[2];
    const float* bq = (const float*)d_in[3];
    const float* Wo = (const float*)d_in[4];
    const float* bo = (const float*)d_in[5];
    float* out = (float*)d_out;

    float *qbuf;
    __nv_bfloat16 *gh, *gl, *xh, *xl, *wqh, *wql, *woh, *wol;
    cudaGetSymbolAddress((void**)&qbuf, g_q);
    cudaGetSymbolAddress((void**)&gh,  g_gh);  cudaGetSymbolAddress((void**)&gl,  g_gl);
    cudaGetSymbolAddress((void**)&xh,  g_xh);  cudaGetSymbolAddress((void**)&xl,  g_xl);
    cudaGetSymbolAddress((void**)&wqh, g_wqh); cudaGetSymbolAddress((void**)&wql, g_wql);
    cudaGetSymbolAddress((void**)&woh, g_woh); cudaGetSymbolAddress((void**)&wol, g_wol);

    cudaFuncSetAttribute(gemm_mma_kernel,
                         cudaFuncAttributeMaxDynamicSharedMemorySize, GEMM_SMEM);

    dim3 gGemm(DIM_ / 128, M_ / 128);           // (4, 32) = 128 CTAs
    dim3 gAttn(LQ_ / 128, H_, B_);              // (2, 8, 16) = 256 CTAs
    int prepBlocks = (NG + 2 * NW + 255) / 256;

    prep_kernel<<<prepBlocks, 256>>>(G, Wq, Wo);
    gemm_mma_kernel<<<gGemm, 256, GEMM_SMEM>>>(gh, gl, wqh, wql, bq, qbuf);
    attn_mma_kernel<<<gAttn, 256>>>(L, qbuf, xh, xl);
    gemm_mma_kernel<<<gGemm, 256, GEMM_SMEM>>>(xh, xl, woh, wol, bo, out);
}

// round 6
// speedup vs baseline: 7.2993x; 1.0252x over previous
#include <cuda_runtime.h>
#include <cuda_bf16.h>
#include <stdint.h>

#define B_   16
#define LK_  2048
#define LQ_  256
#define DIM_ 512
#define H_   8
#define DK_  64
#define M_   (B_ * LQ_)     // 4096

// ---------------- helpers ----------------
__device__ __forceinline__ uint32_t pack_bf16(float x, float y) {
    __nv_bfloat162 h = __float22bfloat162_rn(make_float2(x, y));
    return *(uint32_t*)&h;
}
__device__ __forceinline__ void pack_split(float x, float y, uint32_t& hi, uint32_t& lo) {
    __nv_bfloat162 h = __float22bfloat162_rn(make_float2(x, y));
    float2 hf = __bfloat1622float2(h);
    __nv_bfloat162 l = __float22bfloat162_rn(make_float2(x - hf.x, y - hf.y));
    hi = *(uint32_t*)&h;
    lo = *(uint32_t*)&l;
}
__device__ __forceinline__ void ldsm4(uint32_t* r, uint32_t addr) {
    asm volatile("ldmatrix.sync.aligned.m8n8.x4.shared.b16 {%0,%1,%2,%3}, [%4];"
        : "=r"(r[0]), "=r"(r[1]), "=r"(r[2]), "=r"(r[3]) : "r"(addr));
}
__device__ __forceinline__ void ldsm4t(uint32_t* r, uint32_t addr) {
    asm volatile("ldmatrix.sync.aligned.m8n8.x4.trans.shared.b16 {%0,%1,%2,%3}, [%4];"
        : "=r"(r[0]), "=r"(r[1]), "=r"(r[2]), "=r"(r[3]) : "r"(addr));
}
__device__ __forceinline__ void mma16816(float* c, const uint32_t* a,
                                         uint32_t b0, uint32_t b1) {
    asm volatile("mma.sync.aligned.m16n8k16.row.col.f32.bf16.bf16.f32 "
        "{%0,%1,%2,%3}, {%4,%5,%6,%7}, {%8,%9}, {%0,%1,%2,%3};"
        : "+f"(c[0]), "+f"(c[1]), "+f"(c[2]), "+f"(c[3])
        : "r"(a[0]), "r"(a[1]), "r"(a[2]), "r"(a[3]), "r"(b0), "r"(b1));
}
__device__ __forceinline__ void cp16(uint32_t dst, const void* src) {
    asm volatile("cp.async.cg.shared.global [%0], [%1], 16;" :: "r"(dst), "l"(src));
}

// ---------------- scratch (__device__ globals) ----------------
__device__ float         g_q  [M_ * DIM_];
__device__ __nv_bfloat16 g_gh [M_ * DIM_], g_gl [M_ * DIM_];
__device__ __nv_bfloat16 g_xh [M_ * DIM_], g_xl [M_ * DIM_];
__device__ __nv_bfloat16 g_wqh[DIM_ * DIM_], g_wql[DIM_ * DIM_];
__device__ __nv_bfloat16 g_woh[DIM_ * DIM_], g_wol[DIM_ * DIM_];

// ---------------------------------------------------------------------------
// Prep: split G, Wq, Wo into bf16 hi/lo
// ---------------------------------------------------------------------------
#define NG (M_ * DIM_ / 2)
#define NW (DIM_ * DIM_ / 2)

__global__ void prep_kernel(const float* __restrict__ G,
                            const float* __restrict__ Wq,
                            const float* __restrict__ Wo) {
    int i = blockIdx.x * blockDim.x + threadIdx.x;
    uint32_t h, l;
    if (i < NG) {
        float2 v = ((const float2*)G)[i];
        pack_split(v.x, v.y, h, l);
        ((uint32_t*)g_gh)[i] = h; ((uint32_t*)g_gl)[i] = l;
    } else if (i < NG + NW) {
        int j = i - NG;
        float2 v = ((const float2*)Wq)[j];
        pack_split(v.x, v.y, h, l);
        ((uint32_t*)g_wqh)[j] = h; ((uint32_t*)g_wql)[j] = l;
    } else if (i < NG + 2 * NW) {
        int j = i - NG - NW;
        float2 v = ((const float2*)Wo)[j];
        pack_split(v.x, v.y, h, l);
        ((uint32_t*)g_woh)[j] = h; ((uint32_t*)g_wol)[j] = l;
    }
}

// ---------------------------------------------------------------------------
// GEMM on mma.sync (unchanged from R5 WIN)
// ---------------------------------------------------------------------------
#define GS_STAGE 65536
#define GS_A_L   16384
#define GS_W_H   32768
#define GEMM_SMEM (2 * GS_STAGE)

__global__ __launch_bounds__(256, 1)
void gemm_mma_kernel(const __nv_bfloat16* __restrict__ Ah,
                     const __nv_bfloat16* __restrict__ Al,
                     const __nv_bfloat16* __restrict__ Wh,
                     const __nv_bfloat16* __restrict__ Wl,
                     const float* __restrict__ bias,
                     float* __restrict__ C) {
    extern __shared__ char sm[];
    const uint32_t sb = (uint32_t)__cvta_generic_to_shared(sm);
    const int tid = threadIdx.x, wid = tid >> 5, lane = tid & 31;
    const int g = lane >> 2, t = lane & 3;
    const int n0 = blockIdx.x * 128, m0 = blockIdx.y * 128;

    int alin[4], wlin[4];
    #pragma unroll
    for (int i = 0; i < 4; ++i) { alin[i] = tid + i * 256; wlin[i] = tid + i * 256; }

    auto issue = [&](int kb, int s) {
        uint32_t base = sb + (uint32_t)s * GS_STAGE;
        #pragma unroll
        for (int i = 0; i < 4; ++i) {
            int ar = alin[i] >> 3, ac = alin[i] & 7;
            uint32_t ad = base + (uint32_t)(((ar * 128 + ac * 16) ^ ((ar & 7) << 4)));
            size_t asrc = (size_t)(m0 + ar) * DIM_ + kb * 64 + ac * 8;
            cp16(ad,           Ah + asrc);
            cp16(ad + GS_A_L,  Al + asrc);
            int wr = wlin[i] >> 4, wc = wlin[i] & 15;
            uint32_t wd = base + GS_W_H +
                          (uint32_t)(((wr * 256 + wc * 16) ^ ((wr & 7) << 4)));
            size_t wsrc = (size_t)(kb * 64 + wr) * DIM_ + n0 + wc * 8;
            cp16(wd,           Wh + wsrc);
            cp16(wd + 16384,   Wl + wsrc);
        }
        asm volatile("cp.async.commit_group;");
    };

    float acc[16][4];
    #pragma unroll
    for (int j = 0; j < 16; ++j) {
        acc[j][0] = 0.f; acc[j][1] = 0.f; acc[j][2] = 0.f; acc[j][3] = 0.f;
    }

    const uint32_t xr   = (uint32_t)(lane & 7) << 4;
    const uint32_t cH   = (uint32_t)(lane >> 4) * 16;
    const uint32_t aRow = (uint32_t)((wid * 16 + (lane & 15)) * 128);
    const uint32_t wRow = (uint32_t)((lane & 15) * 256);

    issue(0, 0);
    for (int kb = 0; kb < 8; ++kb) {
        if (kb < 7) {
            issue(kb + 1, (kb + 1) & 1);
            asm volatile("cp.async.wait_group 1;");
        } else {
            asm volatile("cp.async.wait_group 0;");
        }
        __syncthreads();

        uint32_t base = sb + (uint32_t)(kb & 1) * GS_STAGE;
        uint32_t ahf[4][4], alf[4][4];
        #pragma unroll
        for (int s = 0; s < 4; ++s) {
            uint32_t ad = base + aRow + (((uint32_t)(s * 32) + cH) ^ xr);
            ldsm4(ahf[s], ad);
            ldsm4(alf[s], ad + GS_A_L);
        }
        #pragma unroll
        for (int s = 0; s < 4; ++s) {
            #pragma unroll
            for (int nf = 0; nf < 8; ++nf) {
                uint32_t wa = base + GS_W_H + (uint32_t)(s * 4096) + wRow +
                              (((uint32_t)(nf * 32) + cH) ^ xr);
                uint32_t wh[4], wl[4];
                ldsm4t(wh, wa);
                ldsm4t(wl, wa + 16384);
                mma16816(acc[2 * nf],     ahf[s], wh[0], wh[1]);
                mma16816(acc[2 * nf + 1], ahf[s], wh[2], wh[3]);
                mma16816(acc[2 * nf],     ahf[s], wl[0], wl[1]);
                mma16816(acc[2 * nf + 1], ahf[s], wl[2], wl[3]);
                mma16816(acc[2 * nf],     alf[s], wh[0], wh[1]);
                mma16816(acc[2 * nf + 1], alf[s], wh[2], wh[3]);
            }
        }
        __syncthreads();
    }

    const int r0 = m0 + wid * 16 + g;
    #pragma unroll
    for (int j = 0; j < 16; ++j) {
        int c = n0 + j * 8 + 2 * t;
        float2 bv = *(const float2*)&bias[c];
        *(float2*)&C[(size_t)r0 * DIM_ + c] =
            make_float2(acc[j][0] + bv.x, acc[j][1] + bv.y);
        *(float2*)&C[(size_t)(r0 + 8) * DIM_ + c] =
            make_float2(acc[j][2] + bv.x, acc[j][3] + bv.y);
    }
}

// ---------------------------------------------------------------------------
// FA2 on mma.sync, half-tile (64-token) double buffer, 2 CTAs/SM target.
// 32 half-tiles of 64 tokens; one __syncthreads per half-tile.
// ---------------------------------------------------------------------------
__global__ __launch_bounds__(256, 2)
void attn_mma_kernel(const float* __restrict__ Lp, const float* __restrict__ Qp,
                     __nv_bfloat16* __restrict__ Xh, __nv_bfloat16* __restrict__ Xl) {
    __shared__ __nv_bfloat16 KH[2][64 * 64];   // [buf][row][d] hi
    __shared__ __nv_bfloat16 KL[2][64 * 64];   // lo

    const int tid  = threadIdx.x;
    const int wid  = tid >> 5;
    const int lane = tid & 31;
    const int g = lane >> 2, t = lane & 3;
    const int qb = blockIdx.x, h = blockIdx.y, b = blockIdx.z;
    const float scale = 0.00552427172801990775f;   // 1/(8*sqrt(512))

    const uint32_t khb = (uint32_t)__cvta_generic_to_shared(KH);
    const uint32_t klb = (uint32_t)__cvta_generic_to_shared(KL);

    // ---- Q A-fragments (bf16, pre-scaled) ----
    uint32_t qa[4][4];
    {
        const float* qbase =
            Qp + ((size_t)b * LQ_ + (size_t)qb * 128 + wid * 16) * DIM_ + h * DK_;
        #pragma unroll
        for (int s = 0; s < 4; ++s) {
            int d0 = 16 * s + 2 * t;
            float2 v0 = *(const float2*)&qbase[(size_t)g * DIM_ + d0];
            float2 v1 = *(const float2*)&qbase[(size_t)(g + 8) * DIM_ + d0];
            float2 v2 = *(const float2*)&qbase[(size_t)g * DIM_ + d0 + 8];
            float2 v3 = *(const float2*)&qbase[(size_t)(g + 8) * DIM_ + d0 + 8];
            qa[s][0] = pack_bf16(v0.x * scale, v0.y * scale);
            qa[s][1] = pack_bf16(v1.x * scale, v1.y * scale);
            qa[s][2] = pack_bf16(v2.x * scale, v2.y * scale);
            qa[s][3] = pack_bf16(v3.x * scale, v3.y * scale);
        }
    }

    // loader mapping: 64 rows x 64 d per half, 4 float4/thread
    const int lr0 = tid >> 4;          // 0..15
    const int ld4 = (tid & 15) * 4;    // 0..60
    const float* lbase = Lp + (size_t)b * LK_ * DIM_ + h * DK_;

    float4 pf[4];
    #pragma unroll
    for (int it = 0; it < 4; ++it)
        pf[it] = *(const float4*)&lbase[(size_t)(lr0 + it * 16) * DIM_ + ld4];

    // store pf -> buf
    auto store_half = [&](int buf) {
        #pragma unroll
        for (int it = 0; it < 4; ++it) {
            int r = lr0 + it * 16;
            uint32_t hx, lx, hy, ly;
            pack_split(pf[it].x, pf[it].y, hx, lx);
            pack_split(pf[it].z, pf[it].w, hy, ly);
            uint32_t off = (uint32_t)(r * 128 + ld4 * 2);
            off = off ^ ((off >> 3) & 0x70);
            *(uint2*)((char*)KH[buf] + off) = make_uint2(hx, hy);
            *(uint2*)((char*)KL[buf] + off) = make_uint2(lx, ly);
        }
    };
    auto load_half = [&](int j) {
        #pragma unroll
        for (int it = 0; it < 4; ++it)
            pf[it] = *(const float4*)
                &lbase[(size_t)(j * 64 + lr0 + it * 16) * DIM_ + ld4];
    };

    float oacc[8][4];
    #pragma unroll
    for (int i = 0; i < 8; ++i)
        #pragma unroll
        for (int j = 0; j < 4; ++j) oacc[i][j] = 0.f;
    float lacc0 = 0.f, lacc1 = 0.f;

    const uint32_t sXor  = (uint32_t)(lane & 7) << 4;
    const uint32_t sRow  = (uint32_t)(lane & 7) * 128;
    const uint32_t sOff0 = sRow + ((((uint32_t)(lane >> 3)) * 16 +  0) ^ sXor);
    const uint32_t sOff1 = sRow + ((((uint32_t)(lane >> 3)) * 16 + 64) ^ sXor);
    const uint32_t vRow  = (uint32_t)(lane & 15) * 128;
    const uint32_t vD    = (uint32_t)(lane >> 4) * 16;

    // prologue: buf0 <- half 0; pf <- half 1
    store_half(0);
    load_half(1);
    __syncthreads();

    for (int i = 0; i < 32; ++i) {
        const uint32_t bo = (uint32_t)((i & 1) * 8192);

        // ---- S over 8 nf (8 tokens each) ----
        float sacc[8][4];
        #pragma unroll
        for (int nf = 0; nf < 8; ++nf) {
            sacc[nf][0] = 0.f; sacc[nf][1] = 0.f;
            sacc[nf][2] = 0.f; sacc[nf][3] = 0.f;
        }
        #pragma unroll
        for (int nf = 0; nf < 8; ++nf) {
            uint32_t bfr[8];
            ldsm4(bfr + 0, khb + bo + (uint32_t)(nf * 1024) + sOff0);
            ldsm4(bfr + 4, khb + bo + (uint32_t)(nf * 1024) + sOff1);
            #pragma unroll
            for (int s = 0; s < 4; ++s)
                mma16816(sacc[nf], qa[s], bfr[2 * s], bfr[2 * s + 1]);
        }

        // ---- exp ----
        #pragma unroll
        for (int nf = 0; nf < 8; ++nf) {
            float p0 = __expf(sacc[nf][0]);
            float p1 = __expf(sacc[nf][1]);
            float p2 = __expf(sacc[nf][2]);
            float p3 = __expf(sacc[nf][3]);
            lacc0 += p0 + p1;
            lacc1 += p2 + p3;
            sacc[nf][0] = p0; sacc[nf][1] = p1;
            sacc[nf][2] = p2; sacc[nf][3] = p3;
        }

        // ---- O += P V (3-term hi/lo) ----
        #pragma unroll
        for (int u = 0; u < 4; ++u) {
            uint32_t pah[4], pal[4];
            pack_split(sacc[2 * u][0],     sacc[2 * u][1],     pah[0], pal[0]);
            pack_split(sacc[2 * u][2],     sacc[2 * u][3],     pah[1], pal[1]);
            pack_split(sacc[2 * u + 1][0], sacc[2 * u + 1][1], pah[2], pal[2]);
            pack_split(sacc[2 * u + 1][2], sacc[2 * u + 1][3], pah[3], pal[3]);
            #pragma unroll
            for (int dfp = 0; dfp < 4; ++dfp) {
                uint32_t voff = bo + vRow + (uint32_t)(u * 2048)
                              + (((uint32_t)(dfp * 32) + vD) ^ sXor);
                uint32_t vh[4], vl[4];
                ldsm4t(vh, khb + voff);
                ldsm4t(vl, klb + voff);
                mma16816(oacc[2 * dfp],     pah, vh[0], vh[1]);
                mma16816(oacc[2 * dfp + 1], pah, vh[2], vh[3]);
                mma16816(oacc[2 * dfp],     pah, vl[0], vl[1]);
                mma16816(oacc[2 * dfp + 1], pah, vl[2], vl[3]);
                mma16816(oacc[2 * dfp],     pal, vh[0], vh[1]);
                mma16816(oacc[2 * dfp + 1], pal, vh[2], vh[3]);
            }
        }

        // ---- stage next halves ----
        if (i < 31) {
            store_half((i + 1) & 1);
            if (i < 30) load_half(i + 2);
            __syncthreads();
        }
    }

    // ---- epilogue ----
    lacc0 += __shfl_xor_sync(0xffffffffu, lacc0, 1);
    lacc0 += __shfl_xor_sync(0xffffffffu, lacc0, 2);
    lacc1 += __shfl_xor_sync(0xffffffffu, lacc1, 1);
    lacc1 += __shfl_xor_sync(0xffffffffu, lacc1, 2);
    float inv0 = 1.f / lacc0, inv1 = 1.f / lacc1;

    size_t r0 = ((size_t)b * LQ_ + (size_t)qb * 128 + wid * 16 + g) * DIM_ + h * DK_;
    size_t r1 = r0 + 8 * DIM_;
    #pragma unroll
    for (int df = 0; df < 8; ++df) {
        int c = df * 8 + 2 * t;
        uint32_t h0, l0, h1, l1;
        pack_split(oacc[df][0] * inv0, oacc[df][1] * inv0, h0, l0);
        pack_split(oacc[df][2] * inv1, oacc[df][3] * inv1, h1, l1);
        *(uint32_t*)((char*)Xh + (r0 + c) * 2) = h0;
        *(uint32_t*)((char*)Xl + (r0 + c) * 2) = l0;
        *(uint32_t*)((char*)Xh + (r1 + c) * 2) = h1;
        *(uint32_t*)((char*)Xl + (r1 + c) * 2) = l1;
    }
}

// ---------------------------------------------------------------------------
extern "C" void kernel_launch(void* const* d_in, const int* in_sizes, int n_in,
                              void* d_out, int out_size) {
    const float* L  = (const float*)d_in[0];
    const float* G  = (const float*)d_in[1];
    const float* Wq = (const float*)d_in[2];
    const float* bq = (const float*)d_in[3];
    const float* Wo = (const float*)d_in[4];
    const float* bo = (const float*)d_in[5];
    float* out = (float*)d_out;

    float *qbuf;
    __nv_bfloat16 *gh, *gl, *xh, *xl, *wqh, *wql, *woh, *wol;
    cudaGetSymbolAddress((void**)&qbuf, g_q);
    cudaGetSymbolAddress((void**)&gh,  g_gh);  cudaGetSymbolAddress((void**)&gl,  g_gl);
    cudaGetSymbolAddress((void**)&xh,  g_xh);  cudaGetSymbolAddress((void**)&xl,  g_xl);
    cudaGetSymbolAddress((void**)&wqh, g_wqh); cudaGetSymbolAddress((void**)&wql, g_wql);
    cudaGetSymbolAddress((void**)&woh, g_woh); cudaGetSymbolAddress((void**)&wol, g_wol);

    cudaFuncSetAttribute(gemm_mma_kernel,
                         cudaFuncAttributeMaxDynamicSharedMemorySize, GEMM_SMEM);

    dim3 gGemm(DIM_ / 128, M_ / 128);           // 128 CTAs
    dim3 gAttn(LQ_ / 128, H_, B_);              // 256 CTAs
    int prepBlocks = (NG + 2 * NW + 255) / 256;

    prep_kernel<<<prepBlocks, 256>>>(G, Wq, Wo);
    gemm_mma_kernel<<<gGemm, 256, GEMM_SMEM>>>(gh, gl, wqh, wql, bq, qbuf);
    attn_mma_kernel<<<gAttn, 256>>>(L, qbuf, xh, xl);
    gemm_mma_kernel<<<gGemm, 256, GEMM_SMEM>>>(xh, xl, woh, wol, bo, out);
}

// round 7
// speedup vs baseline: 11.0540x; 1.5144x over previous
#include <cuda_runtime.h>
#include <cuda_fp16.h>
#include <stdint.h>

#define B_   16
#define LK_  2048
#define LQ_  256
#define DIM_ 512
#define H_   8
#define DK_  64
#define M_   (B_ * LQ_)     // 4096

// ---------------- helpers ----------------
__device__ __forceinline__ uint32_t pack_h2(float x, float y) {
    __half2 h = __float22half2_rn(make_float2(x, y));
    return *(uint32_t*)&h;
}
__device__ __forceinline__ void pack_split_h(float x, float y,
                                             uint32_t& hi, uint32_t& lo) {
    __half2 h = __float22half2_rn(make_float2(x, y));
    float2 hf = __half22float2(h);
    __half2 l = __float22half2_rn(make_float2(x - hf.x, y - hf.y));
    hi = *(uint32_t*)&h;
    lo = *(uint32_t*)&l;
}
__device__ __forceinline__ void ldsm4(uint32_t* r, uint32_t addr) {
    asm volatile("ldmatrix.sync.aligned.m8n8.x4.shared.b16 {%0,%1,%2,%3}, [%4];"
        : "=r"(r[0]), "=r"(r[1]), "=r"(r[2]), "=r"(r[3]) : "r"(addr));
}
__device__ __forceinline__ void ldsm4t(uint32_t* r, uint32_t addr) {
    asm volatile("ldmatrix.sync.aligned.m8n8.x4.trans.shared.b16 {%0,%1,%2,%3}, [%4];"
        : "=r"(r[0]), "=r"(r[1]), "=r"(r[2]), "=r"(r[3]) : "r"(addr));
}
__device__ __forceinline__ void mma16816(float* c, const uint32_t* a,
                                         uint32_t b0, uint32_t b1) {
    asm volatile("mma.sync.aligned.m16n8k16.row.col.f32.f16.f16.f32 "
        "{%0,%1,%2,%3}, {%4,%5,%6,%7}, {%8,%9}, {%0,%1,%2,%3};"
        : "+f"(c[0]), "+f"(c[1]), "+f"(c[2]), "+f"(c[3])
        : "r"(a[0]), "r"(a[1]), "r"(a[2]), "r"(a[3]), "r"(b0), "r"(b1));
}
__device__ __forceinline__ void cp16(uint32_t dst, const void* src) {
    asm volatile("cp.async.cg.shared.global [%0], [%1], 16;" :: "r"(dst), "l"(src));
}

// ---------------- scratch (__device__ globals) ----------------
__device__ float  g_q  [M_ * DIM_];
__device__ __half g_gh [M_ * DIM_];
__device__ __half g_xh [M_ * DIM_];
__device__ __half g_wqh[DIM_ * DIM_], g_wql[DIM_ * DIM_];
__device__ __half g_woh[DIM_ * DIM_], g_wol[DIM_ * DIM_];

// ---------------------------------------------------------------------------
// Prep: G -> fp16; Wq, Wo -> fp16 hi/lo
// ---------------------------------------------------------------------------
#define NG (M_ * DIM_ / 2)
#define NW (DIM_ * DIM_ / 2)

__global__ void prep_kernel(const float* __restrict__ G,
                            const float* __restrict__ Wq,
                            const float* __restrict__ Wo) {
    int i = blockIdx.x * blockDim.x + threadIdx.x;
    uint32_t h, l;
    if (i < NG) {
        float2 v = ((const float2*)G)[i];
        ((uint32_t*)g_gh)[i] = pack_h2(v.x, v.y);
    } else if (i < NG + NW) {
        int j = i - NG;
        float2 v = ((const float2*)Wq)[j];
        pack_split_h(v.x, v.y, h, l);
        ((uint32_t*)g_wqh)[j] = h; ((uint32_t*)g_wql)[j] = l;
    } else if (i < NG + 2 * NW) {
        int j = i - NG - NW;
        float2 v = ((const float2*)Wo)[j];
        pack_split_h(v.x, v.y, h, l);
        ((uint32_t*)g_woh)[j] = h; ((uint32_t*)g_wol)[j] = l;
    }
}

// ---------------------------------------------------------------------------
// GEMM on mma.sync fp16: C = A @ (Wh + Wl) + bias, 2-term.
// BM=BN=128, BK=64, 8 warps. cp.async double buffer.
// A smem [m][k] 128B rows; W smem [k][n] 256B rows.
// ---------------------------------------------------------------------------
#define GS_STAGE 49152
#define GS_W_H   16384
#define GS_W_L   32768
#define GEMM_SMEM (2 * GS_STAGE)   // 96 KB

__global__ __launch_bounds__(256, 1)
void gemm_mma_kernel(const __half* __restrict__ Ah,
                     const __half* __restrict__ Wh,
                     const __half* __restrict__ Wl,
                     const float* __restrict__ bias,
                     float* __restrict__ C) {
    extern __shared__ char sm[];
    const uint32_t sb = (uint32_t)__cvta_generic_to_shared(sm);
    const int tid = threadIdx.x, wid = tid >> 5, lane = tid & 31;
    const int g = lane >> 2, t = lane & 3;
    const int n0 = blockIdx.x * 128, m0 = blockIdx.y * 128;

    auto issue = [&](int kb, int s) {
        uint32_t base = sb + (uint32_t)s * GS_STAGE;
        #pragma unroll
        for (int i = 0; i < 4; ++i) {
            int lin = tid + i * 256;
            int ar = lin >> 3, ac = lin & 7;
            uint32_t ad = base + (uint32_t)(((ar * 128 + ac * 16) ^ ((ar & 7) << 4)));
            cp16(ad, Ah + (size_t)(m0 + ar) * DIM_ + kb * 64 + ac * 8);
            int wr = lin >> 4, wc = lin & 15;
            uint32_t wo = (uint32_t)(((wr * 256 + wc * 16) ^ ((wr & 7) << 4)));
            size_t wsrc = (size_t)(kb * 64 + wr) * DIM_ + n0 + wc * 8;
            cp16(base + GS_W_H + wo, Wh + wsrc);
            cp16(base + GS_W_L + wo, Wl + wsrc);
        }
        asm volatile("cp.async.commit_group;");
    };

    float acc[16][4];
    #pragma unroll
    for (int j = 0; j < 16; ++j) {
        acc[j][0] = 0.f; acc[j][1] = 0.f; acc[j][2] = 0.f; acc[j][3] = 0.f;
    }

    const uint32_t xr   = (uint32_t)(lane & 7) << 4;
    const uint32_t cH   = (uint32_t)(lane >> 4) * 16;
    const uint32_t aRow = (uint32_t)((wid * 16 + (lane & 15)) * 128);
    const uint32_t wRow = (uint32_t)((lane & 15) * 256);

    issue(0, 0);
    for (int kb = 0; kb < 8; ++kb) {
        if (kb < 7) {
            issue(kb + 1, (kb + 1) & 1);
            asm volatile("cp.async.wait_group 1;");
        } else {
            asm volatile("cp.async.wait_group 0;");
        }
        __syncthreads();

        uint32_t base = sb + (uint32_t)(kb & 1) * GS_STAGE;
        uint32_t ahf[4][4];
        #pragma unroll
        for (int s = 0; s < 4; ++s)
            ldsm4(ahf[s], base + aRow + (((uint32_t)(s * 32) + cH) ^ xr));

        #pragma unroll
        for (int s = 0; s < 4; ++s) {
            #pragma unroll
            for (int nf = 0; nf < 8; ++nf) {
                uint32_t wo = (uint32_t)(s * 4096) + wRow +
                              (((uint32_t)(nf * 32) + cH) ^ xr);
                uint32_t wh[4], wl[4];
                ldsm4t(wh, base + GS_W_H + wo);
                ldsm4t(wl, base + GS_W_L + wo);
                mma16816(acc[2 * nf],     ahf[s], wh[0], wh[1]);
                mma16816(acc[2 * nf + 1], ahf[s], wh[2], wh[3]);
                mma16816(acc[2 * nf],     ahf[s], wl[0], wl[1]);
                mma16816(acc[2 * nf + 1], ahf[s], wl[2], wl[3]);
            }
        }
        __syncthreads();
    }

    const int r0 = m0 + wid * 16 + g;
    #pragma unroll
    for (int j = 0; j < 16; ++j) {
        int c = n0 + j * 8 + 2 * t;
        float2 bv = *(const float2*)&bias[c];
        *(float2*)&C[(size_t)r0 * DIM_ + c] =
            make_float2(acc[j][0] + bv.x, acc[j][1] + bv.y);
        *(float2*)&C[(size_t)(r0 + 8) * DIM_ + c] =
            make_float2(acc[j][2] + bv.x, acc[j][3] + bv.y);
    }
}

// ---------------------------------------------------------------------------
// FA2 on mma.sync fp16: S 1-term, PV 1-term. Half-tile double buffer.
// ---------------------------------------------------------------------------
__global__ __launch_bounds__(256, 2)
void attn_mma_kernel(const float* __restrict__ Lp, const float* __restrict__ Qp,
                     __half* __restrict__ Xh) {
    __shared__ __half KH[2][64 * 64];   // [buf][row][d]

    const int tid  = threadIdx.x;
    const int wid  = tid >> 5;
    const int lane = tid & 31;
    const int g = lane >> 2, t = lane & 3;
    const int qb = blockIdx.x, h = blockIdx.y, b = blockIdx.z;
    const float scale = 0.00552427172801990775f;   // 1/(8*sqrt(512))

    const uint32_t khb = (uint32_t)__cvta_generic_to_shared(KH);

    // ---- Q A-fragments (fp16, pre-scaled) ----
    uint32_t qa[4][4];
    {
        const float* qbase =
            Qp + ((size_t)b * LQ_ + (size_t)qb * 128 + wid * 16) * DIM_ + h * DK_;
        #pragma unroll
        for (int s = 0; s < 4; ++s) {
            int d0 = 16 * s + 2 * t;
            float2 v0 = *(const float2*)&qbase[(size_t)g * DIM_ + d0];
            float2 v1 = *(const float2*)&qbase[(size_t)(g + 8) * DIM_ + d0];
            float2 v2 = *(const float2*)&qbase[(size_t)g * DIM_ + d0 + 8];
            float2 v3 = *(const float2*)&qbase[(size_t)(g + 8) * DIM_ + d0 + 8];
            qa[s][0] = pack_h2(v0.x * scale, v0.y * scale);
            qa[s][1] = pack_h2(v1.x * scale, v1.y * scale);
            qa[s][2] = pack_h2(v2.x * scale, v2.y * scale);
            qa[s][3] = pack_h2(v3.x * scale, v3.y * scale);
        }
    }

    const int lr0 = tid >> 4;          // 0..15
    const int ld4 = (tid & 15) * 4;    // 0..60
    const float* lbase = Lp + (size_t)b * LK_ * DIM_ + h * DK_;

    float4 pf[4];
    #pragma unroll
    for (int it = 0; it < 4; ++it)
        pf[it] = *(const float4*)&lbase[(size_t)(lr0 + it * 16) * DIM_ + ld4];

    auto store_half = [&](int buf) {
        #pragma unroll
        for (int it = 0; it < 4; ++it) {
            int r = lr0 + it * 16;
            uint32_t off = (uint32_t)(r * 128 + ld4 * 2);
            off = off ^ ((off >> 3) & 0x70);
            *(uint2*)((char*)KH[buf] + off) =
                make_uint2(pack_h2(pf[it].x, pf[it].y), pack_h2(pf[it].z, pf[it].w));
        }
    };
    auto load_half = [&](int j) {
        #pragma unroll
        for (int it = 0; it < 4; ++it)
            pf[it] = *(const float4*)
                &lbase[(size_t)(j * 64 + lr0 + it * 16) * DIM_ + ld4];
    };

    float oacc[8][4];
    #pragma unroll
    for (int i = 0; i < 8; ++i)
        #pragma unroll
        for (int j = 0; j < 4; ++j) oacc[i][j] = 0.f;
    float lacc0 = 0.f, lacc1 = 0.f;

    const uint32_t sXor  = (uint32_t)(lane & 7) << 4;
    const uint32_t sRow  = (uint32_t)(lane & 7) * 128;
    const uint32_t sOff0 = sRow + ((((uint32_t)(lane >> 3)) * 16 +  0) ^ sXor);
    const uint32_t sOff1 = sRow + ((((uint32_t)(lane >> 3)) * 16 + 64) ^ sXor);
    const uint32_t vRow  = (uint32_t)(lane & 15) * 128;
    const uint32_t vD    = (uint32_t)(lane >> 4) * 16;

    store_half(0);
    load_half(1);
    __syncthreads();

    for (int i = 0; i < 32; ++i) {
        const uint32_t bo = (uint32_t)((i & 1) * 8192);

        // ---- S = Q K^T (1 fp16 term) ----
        float sacc[8][4];
        #pragma unroll
        for (int nf = 0; nf < 8; ++nf) {
            sacc[nf][0] = 0.f; sacc[nf][1] = 0.f;
            sacc[nf][2] = 0.f; sacc[nf][3] = 0.f;
        }
        #pragma unroll
        for (int nf = 0; nf < 8; ++nf) {
            uint32_t bfr[8];
            ldsm4(bfr + 0, khb + bo + (uint32_t)(nf * 1024) + sOff0);
            ldsm4(bfr + 4, khb + bo + (uint32_t)(nf * 1024) + sOff1);
            #pragma unroll
            for (int s = 0; s < 4; ++s)
                mma16816(sacc[nf], qa[s], bfr[2 * s], bfr[2 * s + 1]);
        }

        // ---- exp ----
        #pragma unroll
        for (int nf = 0; nf < 8; ++nf) {
            float p0 = __expf(sacc[nf][0]);
            float p1 = __expf(sacc[nf][1]);
            float p2 = __expf(sacc[nf][2]);
            float p3 = __expf(sacc[nf][3]);
            lacc0 += p0 + p1;
            lacc1 += p2 + p3;
            sacc[nf][0] = p0; sacc[nf][1] = p1;
            sacc[nf][2] = p2; sacc[nf][3] = p3;
        }

        // ---- O += P V (1 fp16 term) ----
        #pragma unroll
        for (int u = 0; u < 4; ++u) {
            uint32_t pa[4];
            pa[0] = pack_h2(sacc[2 * u][0],     sacc[2 * u][1]);
            pa[1] = pack_h2(sacc[2 * u][2],     sacc[2 * u][3]);
            pa[2] = pack_h2(sacc[2 * u + 1][0], sacc[2 * u + 1][1]);
            pa[3] = pack_h2(sacc[2 * u + 1][2], sacc[2 * u + 1][3]);
            #pragma unroll
            for (int dfp = 0; dfp < 4; ++dfp) {
                uint32_t voff = bo + vRow + (uint32_t)(u * 2048)
                              + (((uint32_t)(dfp * 32) + vD) ^ sXor);
                uint32_t vh[4];
                ldsm4t(vh, khb + voff);
                mma16816(oacc[2 * dfp],     pa, vh[0], vh[1]);
                mma16816(oacc[2 * dfp + 1], pa, vh[2], vh[3]);
            }
        }

        // ---- stage next halves ----
        if (i < 31) {
            store_half((i + 1) & 1);
            if (i < 30) load_half(i + 2);
            __syncthreads();
        }
    }

    // ---- epilogue ----
    lacc0 += __shfl_xor_sync(0xffffffffu, lacc0, 1);
    lacc0 += __shfl_xor_sync(0xffffffffu, lacc0, 2);
    lacc1 += __shfl_xor_sync(0xffffffffu, lacc1, 1);
    lacc1 += __shfl_xor_sync(0xffffffffu, lacc1, 2);
    float inv0 = 1.f / lacc0, inv1 = 1.f / lacc1;

    size_t r0 = ((size_t)b * LQ_ + (size_t)qb * 128 + wid * 16 + g) * DIM_ + h * DK_;
    size_t r1 = r0 + 8 * DIM_;
    #pragma unroll
    for (int df = 0; df < 8; ++df) {
        int c = df * 8 + 2 * t;
        *(uint32_t*)((char*)Xh + (r0 + c) * 2) =
            pack_h2(oacc[df][0] * inv0, oacc[df][1] * inv0);
        *(uint32_t*)((char*)Xh + (r1 + c) * 2) =
            pack_h2(oacc[df][2] * inv1, oacc[df][3] * inv1);
    }
}

// ---------------------------------------------------------------------------
extern "C" void kernel_launch(void* const* d_in, const int* in_sizes, int n_in,
                              void* d_out, int out_size) {
    const float* L  = (const float*)d_in[0];
    const float* G  = (const float*)d_in[1];
    const float* Wq = (const float*)d_in[2];
    const float* bq = (const float*)d_in[3];
    const float* Wo = (const float*)d_in[4];
    const float* bo = (const float*)d_in[5];
    float* out = (float*)d_out;

    float* qbuf;
    __half *gh, *xh, *wqh, *wql, *woh, *wol;
    cudaGetSymbolAddress((void**)&qbuf, g_q);
    cudaGetSymbolAddress((void**)&gh,  g_gh);
    cudaGetSymbolAddress((void**)&xh,  g_xh);
    cudaGetSymbolAddress((void**)&wqh, g_wqh); cudaGetSymbolAddress((void**)&wql, g_wql);
    cudaGetSymbolAddress((void**)&woh, g_woh); cudaGetSymbolAddress((void**)&wol, g_wol);

    cudaFuncSetAttribute(gemm_mma_kernel,
                         cudaFuncAttributeMaxDynamicSharedMemorySize, GEMM_SMEM);

    dim3 gGemm(DIM_ / 128, M_ / 128);           // 128 CTAs
    dim3 gAttn(LQ_ / 128, H_, B_);              // 256 CTAs
    int prepBlocks = (NG + 2 * NW + 255) / 256;

    prep_kernel<<<prepBlocks, 256>>>(G, Wq, Wo);
    gemm_mma_kernel<<<gGemm, 256, GEMM_SMEM>>>(gh, wqh, wql, bq, qbuf);
    attn_mma_kernel<<<gAttn, 256>>>(L, qbuf, xh);
    gemm_mma_kernel<<<gGemm, 256, GEMM_SMEM>>>(xh, woh, wol, bo, out);
}

// round 8
// speedup vs baseline: 12.2404x; 1.1073x over previous
#include <cuda_runtime.h>
#include <cuda_fp16.h>
#include <stdint.h>

#define B_   16
#define LK_  2048
#define LQ_  256
#define DIM_ 512
#define H_   8
#define DK_  64
#define M_   (B_ * LQ_)     // 4096

// ---------------- helpers ----------------
__device__ __forceinline__ uint32_t pack_h2(float x, float y) {
    __half2 h = __float22half2_rn(make_float2(x, y));
    return *(uint32_t*)&h;
}
__device__ __forceinline__ void pack_split_h(float x, float y,
                                             uint32_t& hi, uint32_t& lo) {
    __half2 h = __float22half2_rn(make_float2(x, y));
    float2 hf = __half22float2(h);
    __half2 l = __float22half2_rn(make_float2(x - hf.x, y - hf.y));
    hi = *(uint32_t*)&h;
    lo = *(uint32_t*)&l;
}
// exp2 of two fp32 values -> fp16x2 (P fragment half-word)
__device__ __forceinline__ uint32_t ex2_h2(float x, float y) {
    uint32_t c = pack_h2(x, y);
    uint32_t r;
    asm("ex2.approx.f16x2 %0, %1;" : "=r"(r) : "r"(c));
    return r;
}
__device__ __forceinline__ void ldsm4(uint32_t* r, uint32_t addr) {
    asm volatile("ldmatrix.sync.aligned.m8n8.x4.shared.b16 {%0,%1,%2,%3}, [%4];"
        : "=r"(r[0]), "=r"(r[1]), "=r"(r[2]), "=r"(r[3]) : "r"(addr));
}
__device__ __forceinline__ void ldsm4t(uint32_t* r, uint32_t addr) {
    asm volatile("ldmatrix.sync.aligned.m8n8.x4.trans.shared.b16 {%0,%1,%2,%3}, [%4];"
        : "=r"(r[0]), "=r"(r[1]), "=r"(r[2]), "=r"(r[3]) : "r"(addr));
}
__device__ __forceinline__ void mma16816(float* c, const uint32_t* a,
                                         uint32_t b0, uint32_t b1) {
    asm volatile("mma.sync.aligned.m16n8k16.row.col.f32.f16.f16.f32 "
        "{%0,%1,%2,%3}, {%4,%5,%6,%7}, {%8,%9}, {%0,%1,%2,%3};"
        : "+f"(c[0]), "+f"(c[1]), "+f"(c[2]), "+f"(c[3])
        : "r"(a[0]), "r"(a[1]), "r"(a[2]), "r"(a[3]), "r"(b0), "r"(b1));
}
__device__ __forceinline__ void cp16(uint32_t dst, const void* src) {
    asm volatile("cp.async.cg.shared.global [%0], [%1], 16;" :: "r"(dst), "l"(src));
}

// ---------------- scratch (__device__ globals) ----------------
__device__ float  g_q  [M_ * DIM_];
__device__ __half g_gh [M_ * DIM_];
__device__ __half g_xh [M_ * DIM_];
__device__ __half g_wqh[DIM_ * DIM_], g_wql[DIM_ * DIM_];
__device__ __half g_woh[DIM_ * DIM_], g_wol[DIM_ * DIM_];

// ---------------------------------------------------------------------------
// Prep: G -> fp16; Wq, Wo -> fp16 hi/lo
// ---------------------------------------------------------------------------
#define NG (M_ * DIM_ / 2)
#define NW (DIM_ * DIM_ / 2)

__global__ void prep_kernel(const float* __restrict__ G,
                            const float* __restrict__ Wq,
                            const float* __restrict__ Wo) {
    int i = blockIdx.x * blockDim.x + threadIdx.x;
    uint32_t h, l;
    if (i < NG) {
        float2 v = ((const float2*)G)[i];
        ((uint32_t*)g_gh)[i] = pack_h2(v.x, v.y);
    } else if (i < NG + NW) {
        int j = i - NG;
        float2 v = ((const float2*)Wq)[j];
        pack_split_h(v.x, v.y, h, l);
        ((uint32_t*)g_wqh)[j] = h; ((uint32_t*)g_wql)[j] = l;
    } else if (i < NG + 2 * NW) {
        int j = i - NG - NW;
        float2 v = ((const float2*)Wo)[j];
        pack_split_h(v.x, v.y, h, l);
        ((uint32_t*)g_woh)[j] = h; ((uint32_t*)g_wol)[j] = l;
    }
}

// ---------------------------------------------------------------------------
// GEMM on mma.sync fp16, 2-term. BM=BN=128, BK=64, 8 warps as 2m x 4n
// (warp tile m64 x n32) -> 32 LDSM per warp per kb instead of 68.
// ---------------------------------------------------------------------------
#define GS_STAGE 49152
#define GS_W_H   16384
#define GS_W_L   32768
#define GEMM_SMEM (2 * GS_STAGE)   // 96 KB

__global__ __launch_bounds__(256, 1)
void gemm_mma_kernel(const __half* __restrict__ Ah,
                     const __half* __restrict__ Wh,
                     const __half* __restrict__ Wl,
                     const float* __restrict__ bias,
                     float* __restrict__ C) {
    extern __shared__ char sm[];
    const uint32_t sb = (uint32_t)__cvta_generic_to_shared(sm);
    const int tid = threadIdx.x, wid = tid >> 5, lane = tid & 31;
    const int g = lane >> 2, t = lane & 3;
    const int wm = wid & 1, wn = wid >> 1;      // 2 m-warps x 4 n-warps
    const int n0 = blockIdx.x * 128, m0 = blockIdx.y * 128;

    auto issue = [&](int kb, int s) {
        uint32_t base = sb + (uint32_t)s * GS_STAGE;
        #pragma unroll
        for (int i = 0; i < 4; ++i) {
            int lin = tid + i * 256;
            int ar = lin >> 3, ac = lin & 7;
            uint32_t ad = base + (uint32_t)(((ar * 128 + ac * 16) ^ ((ar & 7) << 4)));
            cp16(ad, Ah + (size_t)(m0 + ar) * DIM_ + kb * 64 + ac * 8);
            int wr = lin >> 4, wc = lin & 15;
            uint32_t wo = (uint32_t)(((wr * 256 + wc * 16) ^ ((wr & 7) << 4)));
            size_t wsrc = (size_t)(kb * 64 + wr) * DIM_ + n0 + wc * 8;
            cp16(base + GS_W_H + wo, Wh + wsrc);
            cp16(base + GS_W_L + wo, Wl + wsrc);
        }
        asm volatile("cp.async.commit_group;");
    };

    float acc[4][4][4];   // [m-frag][n8-frag][regs]
    #pragma unroll
    for (int i = 0; i < 4; ++i)
        #pragma unroll
        for (int j = 0; j < 4; ++j)
            #pragma unroll
            for (int r = 0; r < 4; ++r) acc[i][j][r] = 0.f;

    const uint32_t xr   = (uint32_t)(lane & 7) << 4;
    const uint32_t cH   = (uint32_t)(lane >> 4) * 16;
    const uint32_t aRow = (uint32_t)((wm * 64 + (lane & 15)) * 128);
    const uint32_t wRow = (uint32_t)((lane & 15) * 256);
    const uint32_t wCol = (uint32_t)(wn * 64);

    issue(0, 0);
    for (int kb = 0; kb < 8; ++kb) {
        if (kb < 7) {
            issue(kb + 1, (kb + 1) & 1);
            asm volatile("cp.async.wait_group 1;");
        } else {
            asm volatile("cp.async.wait_group 0;");
        }
        __syncthreads();

        uint32_t base = sb + (uint32_t)(kb & 1) * GS_STAGE;
        #pragma unroll
        for (int s = 0; s < 4; ++s) {
            uint32_t af[4][4];
            #pragma unroll
            for (int mf = 0; mf < 4; ++mf)
                ldsm4(af[mf], base + aRow + (uint32_t)(mf * 16 * 128)
                              + (((uint32_t)(s * 32) + cH) ^ xr));
            #pragma unroll
            for (int nf = 0; nf < 2; ++nf) {
                uint32_t wo = (uint32_t)(s * 4096) + wRow +
                              ((wCol + (uint32_t)(nf * 32) + cH) ^ xr);
                uint32_t wh[4], wl[4];
                ldsm4t(wh, base + GS_W_H + wo);
                ldsm4t(wl, base + GS_W_L + wo);
                #pragma unroll
                for (int mf = 0; mf < 4; ++mf) {
                    mma16816(acc[mf][2 * nf],     af[mf], wh[0], wh[1]);
                    mma16816(acc[mf][2 * nf + 1], af[mf], wh[2], wh[3]);
                    mma16816(acc[mf][2 * nf],     af[mf], wl[0], wl[1]);
                    mma16816(acc[mf][2 * nf + 1], af[mf], wl[2], wl[3]);
                }
            }
        }
        __syncthreads();
    }

    #pragma unroll
    for (int mf = 0; mf < 4; ++mf) {
        int r0 = m0 + wm * 64 + mf * 16 + g;
        #pragma unroll
        for (int nj = 0; nj < 4; ++nj) {
            int c = n0 + wn * 32 + nj * 8 + 2 * t;
            float2 bv = *(const float2*)&bias[c];
            *(float2*)&C[(size_t)r0 * DIM_ + c] =
                make_float2(acc[mf][nj][0] + bv.x, acc[mf][nj][1] + bv.y);
            *(float2*)&C[(size_t)(r0 + 8) * DIM_ + c] =
                make_float2(acc[mf][nj][2] + bv.x, acc[mf][nj][3] + bv.y);
        }
    }
}

// ---------------------------------------------------------------------------
// FA2 on mma.sync fp16. S in log2 domain (scale includes log2e);
// P = ex2.approx.f16x2(S); l via extra mma against ones-B.
// ---------------------------------------------------------------------------
#define ONES_H2 0x3C003C00u

__global__ __launch_bounds__(256, 2)
void attn_mma_kernel(const float* __restrict__ Lp, const float* __restrict__ Qp,
                     __half* __restrict__ Xh) {
    __shared__ __half KH[2][64 * 64];   // [buf][row][d]

    const int tid  = threadIdx.x;
    const int wid  = tid >> 5;
    const int lane = tid & 31;
    const int g = lane >> 2, t = lane & 3;
    const int qb = blockIdx.x, h = blockIdx.y, b = blockIdx.z;
    // (1/(8*sqrt(512))) * log2(e): S computed directly in log2 domain
    const float scale = 0.00552427172801990775f * 1.44269504088896341f;

    const uint32_t khb = (uint32_t)__cvta_generic_to_shared(KH);

    // ---- Q A-fragments (fp16, pre-scaled into log2 domain) ----
    uint32_t qa[4][4];
    {
        const float* qbase =
            Qp + ((size_t)b * LQ_ + (size_t)qb * 128 + wid * 16) * DIM_ + h * DK_;
        #pragma unroll
        for (int s = 0; s < 4; ++s) {
            int d0 = 16 * s + 2 * t;
            float2 v0 = *(const float2*)&qbase[(size_t)g * DIM_ + d0];
            float2 v1 = *(const float2*)&qbase[(size_t)(g + 8) * DIM_ + d0];
            float2 v2 = *(const float2*)&qbase[(size_t)g * DIM_ + d0 + 8];
            float2 v3 = *(const float2*)&qbase[(size_t)(g + 8) * DIM_ + d0 + 8];
            qa[s][0] = pack_h2(v0.x * scale, v0.y * scale);
            qa[s][1] = pack_h2(v1.x * scale, v1.y * scale);
            qa[s][2] = pack_h2(v2.x * scale, v2.y * scale);
            qa[s][3] = pack_h2(v3.x * scale, v3.y * scale);
        }
    }

    const int lr0 = tid >> 4;          // 0..15
    const int ld4 = (tid & 15) * 4;    // 0..60
    const float* lbase = Lp + (size_t)b * LK_ * DIM_ + h * DK_;

    float4 pf[4];
    #pragma unroll
    for (int it = 0; it < 4; ++it)
        pf[it] = *(const float4*)&lbase[(size_t)(lr0 + it * 16) * DIM_ + ld4];

    auto store_half = [&](int buf) {
        #pragma unroll
        for (int it = 0; it < 4; ++it) {
            int r = lr0 + it * 16;
            uint32_t off = (uint32_t)(r * 128 + ld4 * 2);
            off = off ^ ((off >> 3) & 0x70);
            *(uint2*)((char*)KH[buf] + off) =
                make_uint2(pack_h2(pf[it].x, pf[it].y), pack_h2(pf[it].z, pf[it].w));
        }
    };
    auto load_half = [&](int j) {
        #pragma unroll
        for (int it = 0; it < 4; ++it)
            pf[it] = *(const float4*)
                &lbase[(size_t)(j * 64 + lr0 + it * 16) * DIM_ + ld4];
    };

    float oacc[8][4];
    #pragma unroll
    for (int i = 0; i < 8; ++i)
        #pragma unroll
        for (int j = 0; j < 4; ++j) oacc[i][j] = 0.f;
    float lfrag[4] = {0.f, 0.f, 0.f, 0.f};

    const uint32_t sXor  = (uint32_t)(lane & 7) << 4;
    const uint32_t sRow  = (uint32_t)(lane & 7) * 128;
    const uint32_t sOff0 = sRow + ((((uint32_t)(lane >> 3)) * 16 +  0) ^ sXor);
    const uint32_t sOff1 = sRow + ((((uint32_t)(lane >> 3)) * 16 + 64) ^ sXor);
    const uint32_t vRow  = (uint32_t)(lane & 15) * 128;
    const uint32_t vD    = (uint32_t)(lane >> 4) * 16;

    store_half(0);
    load_half(1);
    __syncthreads();

    for (int i = 0; i < 32; ++i) {
        const uint32_t bo = (uint32_t)((i & 1) * 8192);

        // ---- S = Q K^T (log2 domain) ----
        float sacc[8][4];
        #pragma unroll
        for (int nf = 0; nf < 8; ++nf) {
            sacc[nf][0] = 0.f; sacc[nf][1] = 0.f;
            sacc[nf][2] = 0.f; sacc[nf][3] = 0.f;
        }
        #pragma unroll
        for (int nf = 0; nf < 8; ++nf) {
            uint32_t bfr[8];
            ldsm4(bfr + 0, khb + bo + (uint32_t)(nf * 1024) + sOff0);
            ldsm4(bfr + 4, khb + bo + (uint32_t)(nf * 1024) + sOff1);
            #pragma unroll
            for (int s = 0; s < 4; ++s)
                mma16816(sacc[nf], qa[s], bfr[2 * s], bfr[2 * s + 1]);
        }

        // ---- P = exp2(S) as fp16 frags; l += P @ ones; O += P V ----
        #pragma unroll
        for (int u = 0; u < 4; ++u) {
            uint32_t pa[4];
            pa[0] = ex2_h2(sacc[2 * u][0],     sacc[2 * u][1]);
            pa[1] = ex2_h2(sacc[2 * u][2],     sacc[2 * u][3]);
            pa[2] = ex2_h2(sacc[2 * u + 1][0], sacc[2 * u + 1][1]);
            pa[3] = ex2_h2(sacc[2 * u + 1][2], sacc[2 * u + 1][3]);
            mma16816(lfrag, pa, ONES_H2, ONES_H2);
            #pragma unroll
            for (int dfp = 0; dfp < 4; ++dfp) {
                uint32_t voff = bo + vRow + (uint32_t)(u * 2048)
                              + (((uint32_t)(dfp * 32) + vD) ^ sXor);
                uint32_t vh[4];
                ldsm4t(vh, khb + voff);
                mma16816(oacc[2 * dfp],     pa, vh[0], vh[1]);
                mma16816(oacc[2 * dfp + 1], pa, vh[2], vh[3]);
            }
        }

        // ---- stage next halves ----
        if (i < 31) {
            store_half((i + 1) & 1);
            if (i < 30) load_half(i + 2);
            __syncthreads();
        }
    }

    // ---- epilogue: l came out of the ones-mma (rows g / g+8) ----
    float inv0 = 1.f / lfrag[0], inv1 = 1.f / lfrag[2];

    size_t r0 = ((size_t)b * LQ_ + (size_t)qb * 128 + wid * 16 + g) * DIM_ + h * DK_;
    size_t r1 = r0 + 8 * DIM_;
    #pragma unroll
    for (int df = 0; df < 8; ++df) {
        int c = df * 8 + 2 * t;
        *(uint32_t*)((char*)Xh + (r0 + c) * 2) =
            pack_h2(oacc[df][0] * inv0, oacc[df][1] * inv0);
        *(uint32_t*)((char*)Xh + (r1 + c) * 2) =
            pack_h2(oacc[df][2] * inv1, oacc[df][3] * inv1);
    }
}

// ---------------------------------------------------------------------------
extern "C" void kernel_launch(void* const* d_in, const int* in_sizes, int n_in,
                              void* d_out, int out_size) {
    const float* L  = (const float*)d_in[0];
    const float* G  = (const float*)d_in[1];
    const float* Wq = (const float*)d_in[2];
    const float* bq = (const float*)d_in[3];
    const float* Wo = (const float*)d_in[4];
    const float* bo = (const float*)d_in[5];
    float* out = (float*)d_out;

    float* qbuf;
    __half *gh, *xh, *wqh, *wql, *woh, *wol;
    cudaGetSymbolAddress((void**)&qbuf, g_q);
    cudaGetSymbolAddress((void**)&gh,  g_gh);
    cudaGetSymbolAddress((void**)&xh,  g_xh);
    cudaGetSymbolAddress((void**)&wqh, g_wqh); cudaGetSymbolAddress((void**)&wql, g_wql);
    cudaGetSymbolAddress((void**)&woh, g_woh); cudaGetSymbolAddress((void**)&wol, g_wol);

    cudaFuncSetAttribute(gemm_mma_kernel,
                         cudaFuncAttributeMaxDynamicSharedMemorySize, GEMM_SMEM);

    dim3 gGemm(DIM_ / 128, M_ / 128);           // 128 CTAs
    dim3 gAttn(LQ_ / 128, H_, B_);              // 256 CTAs
    int prepBlocks = (NG + 2 * NW + 255) / 256;

    prep_kernel<<<prepBlocks, 256>>>(G, Wq, Wo);
    gemm_mma_kernel<<<gGemm, 256, GEMM_SMEM>>>(gh, wqh, wql, bq, qbuf);
    attn_mma_kernel<<<gAttn, 256>>>(L, qbuf, xh);
    gemm_mma_kernel<<<gGemm, 256, GEMM_SMEM>>>(xh, woh, wol, bo, out);
}

// round 9
// speedup vs baseline: 12.6805x; 1.0360x over previous
#include <cuda_runtime.h>
#include <cuda_fp16.h>
#include <stdint.h>

#define B_   16
#define LK_  2048
#define LQ_  256
#define DIM_ 512
#define H_   8
#define DK_  64
#define M_   (B_ * LQ_)     // 4096

// ---------------- helpers ----------------
__device__ __forceinline__ uint32_t pack_h2(float x, float y) {
    __half2 h = __float22half2_rn(make_float2(x, y));
    return *(uint32_t*)&h;
}
__device__ __forceinline__ void pack_split_h(float x, float y,
                                             uint32_t& hi, uint32_t& lo) {
    __half2 h = __float22half2_rn(make_float2(x, y));
    float2 hf = __half22float2(h);
    __half2 l = __float22half2_rn(make_float2(x - hf.x, y - hf.y));
    hi = *(uint32_t*)&h;
    lo = *(uint32_t*)&l;
}
__device__ __forceinline__ uint32_t ex2_h2(float x, float y) {
    uint32_t c = pack_h2(x, y);
    uint32_t r;
    asm("ex2.approx.f16x2 %0, %1;" : "=r"(r) : "r"(c));
    return r;
}
__device__ __forceinline__ void ldsm4(uint32_t* r, uint32_t addr) {
    asm volatile("ldmatrix.sync.aligned.m8n8.x4.shared.b16 {%0,%1,%2,%3}, [%4];"
        : "=r"(r[0]), "=r"(r[1]), "=r"(r[2]), "=r"(r[3]) : "r"(addr));
}
__device__ __forceinline__ void ldsm4t(uint32_t* r, uint32_t addr) {
    asm volatile("ldmatrix.sync.aligned.m8n8.x4.trans.shared.b16 {%0,%1,%2,%3}, [%4];"
        : "=r"(r[0]), "=r"(r[1]), "=r"(r[2]), "=r"(r[3]) : "r"(addr));
}
__device__ __forceinline__ void mma16816(float* c, const uint32_t* a,
                                         uint32_t b0, uint32_t b1) {
    asm volatile("mma.sync.aligned.m16n8k16.row.col.f32.f16.f16.f32 "
        "{%0,%1,%2,%3}, {%4,%5,%6,%7}, {%8,%9}, {%0,%1,%2,%3};"
        : "+f"(c[0]), "+f"(c[1]), "+f"(c[2]), "+f"(c[3])
        : "r"(a[0]), "r"(a[1]), "r"(a[2]), "r"(a[3]), "r"(b0), "r"(b1));
}
__device__ __forceinline__ void cp16(uint32_t dst, const void* src) {
    asm volatile("cp.async.cg.shared.global [%0], [%1], 16;" :: "r"(dst), "l"(src));
}

// ---------------- scratch (__device__ globals) ----------------
__device__ float  g_q  [M_ * DIM_];
__device__ __half g_gh [M_ * DIM_];
__device__ __half g_xh [M_ * DIM_];
__device__ __half g_wqh[DIM_ * DIM_], g_wql[DIM_ * DIM_];
__device__ __half g_woh[DIM_ * DIM_], g_wol[DIM_ * DIM_];

// ---------------------------------------------------------------------------
// Prep: G -> fp16; Wq, Wo -> fp16 hi/lo
// ---------------------------------------------------------------------------
#define NG (M_ * DIM_ / 2)
#define NW (DIM_ * DIM_ / 2)

__global__ void prep_kernel(const float* __restrict__ G,
                            const float* __restrict__ Wq,
                            const float* __restrict__ Wo) {
    int i = blockIdx.x * blockDim.x + threadIdx.x;
    uint32_t h, l;
    if (i < NG) {
        float2 v = ((const float2*)G)[i];
        ((uint32_t*)g_gh)[i] = pack_h2(v.x, v.y);
    } else if (i < NG + NW) {
        int j = i - NG;
        float2 v = ((const float2*)Wq)[j];
        pack_split_h(v.x, v.y, h, l);
        ((uint32_t*)g_wqh)[j] = h; ((uint32_t*)g_wql)[j] = l;
    } else if (i < NG + 2 * NW) {
        int j = i - NG - NW;
        float2 v = ((const float2*)Wo)[j];
        pack_split_h(v.x, v.y, h, l);
        ((uint32_t*)g_woh)[j] = h; ((uint32_t*)g_wol)[j] = l;
    }
}

// ---------------------------------------------------------------------------
// GEMM on mma.sync fp16, 2-term. BM=128, BN=64, BK=32, 3-stage cp.async,
// 48KB smem -> 2 CTAs/SM; grid 256 CTAs; 8 warps as 4m x 2n (warp m32 x n32).
// A smem [m128][k32] 64B rows, SW64 swizzle; W smem [k32][n64] 128B rows, SW128.
// ---------------------------------------------------------------------------
#define GK_STAGE 16384
#define GK_WH    8192
#define GK_WL    12288
#define GEMM_SMEM (3 * GK_STAGE)   // 48 KB

__global__ __launch_bounds__(256, 2)
void gemm_mma_kernel(const __half* __restrict__ Ah,
                     const __half* __restrict__ Wh,
                     const __half* __restrict__ Wl,
                     const float* __restrict__ bias,
                     float* __restrict__ C) {
    extern __shared__ char sm[];
    const uint32_t sb = (uint32_t)__cvta_generic_to_shared(sm);
    const int tid = threadIdx.x, wid = tid >> 5, lane = tid & 31;
    const int g = lane >> 2, t = lane & 3;
    const int wm = wid & 3, wn = wid >> 2;      // 4 m-warps x 2 n-warps
    const int n0 = blockIdx.x * 64, m0 = blockIdx.y * 128;

    auto issue = [&](int kb, int st) {
        uint32_t base = sb + (uint32_t)st * GK_STAGE;
        // A: 128 rows x 64B; 512 granules, 2 per thread
        #pragma unroll
        for (int i = 0; i < 2; ++i) {
            int lin = tid + i * 256;
            int row = lin >> 2, c = lin & 3;
            uint32_t off = (uint32_t)(row * 64 + c * 16);
            off ^= (off >> 3) & 0x30;
            cp16(base + off, Ah + (size_t)(m0 + row) * DIM_ + kb * 32 + c * 8);
        }
        // W: 32 rows x 128B per term; 256 granules, 1 per thread per term
        {
            int row = tid >> 3, c = tid & 7;
            uint32_t off = (uint32_t)(row * 128 + c * 16);
            off ^= (off >> 3) & 0x70;
            size_t src = (size_t)(kb * 32 + row) * DIM_ + n0 + c * 8;
            cp16(base + GK_WH + off, Wh + src);
            cp16(base + GK_WL + off, Wl + src);
        }
        asm volatile("cp.async.commit_group;");
    };

    float acc[2][4][4];   // [m-frag][n8-frag][regs]
    #pragma unroll
    for (int i = 0; i < 2; ++i)
        #pragma unroll
        for (int j = 0; j < 4; ++j)
            #pragma unroll
            for (int r = 0; r < 4; ++r) acc[i][j][r] = 0.f;

    // A ldsm addressing (64B rows, SW64)
    const uint32_t aColByte = (uint32_t)((lane >> 4) * 16);
    // W ldsm4t addressing (128B rows, SW128)
    const uint32_t xr   = (uint32_t)(lane & 7) << 4;
    const uint32_t wRowB = (uint32_t)((lane & 15) * 128);
    const uint32_t wD    = (uint32_t)((lane >> 4) * 16);
    const uint32_t wCol  = (uint32_t)(wn * 64);   // bytes: n-offset of warp (32 n * 2B)

    issue(0, 0);
    issue(1, 1);

    for (int kb = 0; kb < 16; ++kb) {
        asm volatile("cp.async.wait_group 1;");
        __syncthreads();
        if (kb + 2 < 16) issue(kb + 2, (kb + 2) % 3);

        uint32_t base = sb + (uint32_t)(kb % 3) * GK_STAGE;
        #pragma unroll
        for (int s = 0; s < 2; ++s) {
            // A frags: m32 x k16
            uint32_t af[2][4];
            #pragma unroll
            for (int mf = 0; mf < 2; ++mf) {
                uint32_t off = (uint32_t)((wm * 32 + mf * 16 + (lane & 15)) * 64)
                             + (uint32_t)(s * 32) + aColByte;
                off ^= (off >> 3) & 0x30;
                ldsm4(af[mf], base + off);
            }
            // W frags + mma, per term, per n16 group
            #pragma unroll
            for (int nq = 0; nq < 2; ++nq) {
                uint32_t wo = (uint32_t)(s * 16 * 128) + wRowB +
                              ((wCol + (uint32_t)(nq * 32) + wD) ^ xr);
                uint32_t bh[4], bl[4];
                ldsm4t(bh, base + GK_WH + wo);
                ldsm4t(bl, base + GK_WL + wo);
                #pragma unroll
                for (int mf = 0; mf < 2; ++mf) {
                    mma16816(acc[mf][2 * nq],     af[mf], bh[0], bh[1]);
                    mma16816(acc[mf][2 * nq + 1], af[mf], bh[2], bh[3]);
                    mma16816(acc[mf][2 * nq],     af[mf], bl[0], bl[1]);
                    mma16816(acc[mf][2 * nq + 1], af[mf], bl[2], bl[3]);
                }
            }
        }
        __syncthreads();
    }

    // epilogue: + bias, fp32 out
    #pragma unroll
    for (int mf = 0; mf < 2; ++mf) {
        int r0 = m0 + wm * 32 + mf * 16 + g;
        #pragma unroll
        for (int nj = 0; nj < 4; ++nj) {
            int c = n0 + wn * 32 + nj * 8 + 2 * t;
            float2 bv = *(const float2*)&bias[c];
            *(float2*)&C[(size_t)r0 * DIM_ + c] =
                make_float2(acc[mf][nj][0] + bv.x, acc[mf][nj][1] + bv.y);
            *(float2*)&C[(size_t)(r0 + 8) * DIM_ + c] =
                make_float2(acc[mf][nj][2] + bv.x, acc[mf][nj][3] + bv.y);
        }
    }
}

// ---------------------------------------------------------------------------
// FA2 on mma.sync fp16 (unchanged from R8 WIN). S in log2 domain;
// P = ex2.approx.f16x2(S); l via mma against ones-B.
// ---------------------------------------------------------------------------
#define ONES_H2 0x3C003C00u

__global__ __launch_bounds__(256, 2)
void attn_mma_kernel(const float* __restrict__ Lp, const float* __restrict__ Qp,
                     __half* __restrict__ Xh) {
    __shared__ __half KH[2][64 * 64];   // [buf][row][d]

    const int tid  = threadIdx.x;
    const int wid  = tid >> 5;
    const int lane = tid & 31;
    const int g = lane >> 2, t = lane & 3;
    const int qb = blockIdx.x, h = blockIdx.y, b = blockIdx.z;
    const float scale = 0.00552427172801990775f * 1.44269504088896341f;

    const uint32_t khb = (uint32_t)__cvta_generic_to_shared(KH);

    uint32_t qa[4][4];
    {
        const float* qbase =
            Qp + ((size_t)b * LQ_ + (size_t)qb * 128 + wid * 16) * DIM_ + h * DK_;
        #pragma unroll
        for (int s = 0; s < 4; ++s) {
            int d0 = 16 * s + 2 * t;
            float2 v0 = *(const float2*)&qbase[(size_t)g * DIM_ + d0];
            float2 v1 = *(const float2*)&qbase[(size_t)(g + 8) * DIM_ + d0];
            float2 v2 = *(const float2*)&qbase[(size_t)g * DIM_ + d0 + 8];
            float2 v3 = *(const float2*)&qbase[(size_t)(g + 8) * DIM_ + d0 + 8];
            qa[s][0] = pack_h2(v0.x * scale, v0.y * scale);
            qa[s][1] = pack_h2(v1.x * scale, v1.y * scale);
            qa[s][2] = pack_h2(v2.x * scale, v2.y * scale);
            qa[s][3] = pack_h2(v3.x * scale, v3.y * scale);
        }
    }

    const int lr0 = tid >> 4;          // 0..15
    const int ld4 = (tid & 15) * 4;    // 0..60
    const float* lbase = Lp + (size_t)b * LK_ * DIM_ + h * DK_;

    float4 pf[4];
    #pragma unroll
    for (int it = 0; it < 4; ++it)
        pf[it] = *(const float4*)&lbase[(size_t)(lr0 + it * 16) * DIM_ + ld4];

    auto store_half = [&](int buf) {
        #pragma unroll
        for (int it = 0; it < 4; ++it) {
            int r = lr0 + it * 16;
            uint32_t off = (uint32_t)(r * 128 + ld4 * 2);
            off = off ^ ((off >> 3) & 0x70);
            *(uint2*)((char*)KH[buf] + off) =
                make_uint2(pack_h2(pf[it].x, pf[it].y), pack_h2(pf[it].z, pf[it].w));
        }
    };
    auto load_half = [&](int j) {
        #pragma unroll
        for (int it = 0; it < 4; ++it)
            pf[it] = *(const float4*)
                &lbase[(size_t)(j * 64 + lr0 + it * 16) * DIM_ + ld4];
    };

    float oacc[8][4];
    #pragma unroll
    for (int i = 0; i < 8; ++i)
        #pragma unroll
        for (int j = 0; j < 4; ++j) oacc[i][j] = 0.f;
    float lfrag[4] = {0.f, 0.f, 0.f, 0.f};

    const uint32_t sXor  = (uint32_t)(lane & 7) << 4;
    const uint32_t sRow  = (uint32_t)(lane & 7) * 128;
    const uint32_t sOff0 = sRow + ((((uint32_t)(lane >> 3)) * 16 +  0) ^ sXor);
    const uint32_t sOff1 = sRow + ((((uint32_t)(lane >> 3)) * 16 + 64) ^ sXor);
    const uint32_t vRow  = (uint32_t)(lane & 15) * 128;
    const uint32_t vD    = (uint32_t)(lane >> 4) * 16;

    store_half(0);
    load_half(1);
    __syncthreads();

    for (int i = 0; i < 32; ++i) {
        const uint32_t bo = (uint32_t)((i & 1) * 8192);

        float sacc[8][4];
        #pragma unroll
        for (int nf = 0; nf < 8; ++nf) {
            sacc[nf][0] = 0.f; sacc[nf][1] = 0.f;
            sacc[nf][2] = 0.f; sacc[nf][3] = 0.f;
        }
        #pragma unroll
        for (int nf = 0; nf < 8; ++nf) {
            uint32_t bfr[8];
            ldsm4(bfr + 0, khb + bo + (uint32_t)(nf * 1024) + sOff0);
            ldsm4(bfr + 4, khb + bo + (uint32_t)(nf * 1024) + sOff1);
            #pragma unroll
            for (int s = 0; s < 4; ++s)
                mma16816(sacc[nf], qa[s], bfr[2 * s], bfr[2 * s + 1]);
        }

        #pragma unroll
        for (int u = 0; u < 4; ++u) {
            uint32_t pa[4];
            pa[0] = ex2_h2(sacc[2 * u][0],     sacc[2 * u][1]);
            pa[1] = ex2_h2(sacc[2 * u][2],     sacc[2 * u][3]);
            pa[2] = ex2_h2(sacc[2 * u + 1][0], sacc[2 * u + 1][1]);
            pa[3] = ex2_h2(sacc[2 * u + 1][2], sacc[2 * u + 1][3]);
            mma16816(lfrag, pa, ONES_H2, ONES_H2);
            #pragma unroll
            for (int dfp = 0; dfp < 4; ++dfp) {
                uint32_t voff = bo + vRow + (uint32_t)(u * 2048)
                              + (((uint32_t)(dfp * 32) + vD) ^ sXor);
                uint32_t vh[4];
                ldsm4t(vh, khb + voff);
                mma16816(oacc[2 * dfp],     pa, vh[0], vh[1]);
                mma16816(oacc[2 * dfp + 1], pa, vh[2], vh[3]);
            }
        }

        if (i < 31) {
            store_half((i + 1) & 1);
            if (i < 30) load_half(i + 2);
            __syncthreads();
        }
    }

    float inv0 = 1.f / lfrag[0], inv1 = 1.f / lfrag[2];

    size_t r0 = ((size_t)b * LQ_ + (size_t)qb * 128 + wid * 16 + g) * DIM_ + h * DK_;
    size_t r1 = r0 + 8 * DIM_;
    #pragma unroll
    for (int df = 0; df < 8; ++df) {
        int c = df * 8 + 2 * t;
        *(uint32_t*)((char*)Xh + (r0 + c) * 2) =
            pack_h2(oacc[df][0] * inv0, oacc[df][1] * inv0);
        *(uint32_t*)((char*)Xh + (r1 + c) * 2) =
            pack_h2(oacc[df][2] * inv1, oacc[df][3] * inv1);
    }
}

// ---------------------------------------------------------------------------
extern "C" void kernel_launch(void* const* d_in, const int* in_sizes, int n_in,
                              void* d_out, int out_size) {
    const float* L  = (const float*)d_in[0];
    const float* G  = (const float*)d_in[1];
    const float* Wq = (const float*)d_in[2];
    const float* bq = (const float*)d_in[3];
    const float* Wo = (const float*)d_in[4];
    const float* bo = (const float*)d_in[5];
    float* out = (float*)d_out;

    float* qbuf;
    __half *gh, *xh, *wqh, *wql, *woh, *wol;
    cudaGetSymbolAddress((void**)&qbuf, g_q);
    cudaGetSymbolAddress((void**)&gh,  g_gh);
    cudaGetSymbolAddress((void**)&xh,  g_xh);
    cudaGetSymbolAddress((void**)&wqh, g_wqh); cudaGetSymbolAddress((void**)&wql, g_wql);
    cudaGetSymbolAddress((void**)&woh, g_woh); cudaGetSymbolAddress((void**)&wol, g_wol);

    cudaFuncSetAttribute(gemm_mma_kernel,
                         cudaFuncAttributeMaxDynamicSharedMemorySize, GEMM_SMEM);

    dim3 gGemm(DIM_ / 64, M_ / 128);            // (8, 32) = 256 CTAs
    dim3 gAttn(LQ_ / 128, H_, B_);              // 256 CTAs
    int prepBlocks = (NG + 2 * NW + 255) / 256;

    prep_kernel<<<prepBlocks, 256>>>(G, Wq, Wo);
    gemm_mma_kernel<<<gGemm, 256, GEMM_SMEM>>>(gh, wqh, wql, bq, qbuf);
    attn_mma_kernel<<<gAttn, 256>>>(L, qbuf, xh);
    gemm_mma_kernel<<<gGemm, 256, GEMM_SMEM>>>(xh, woh, wol, bo, out);
}

// round 11
// speedup vs baseline: 13.0232x; 1.0270x over previous
#include <cuda_runtime.h>
#include <cuda_fp16.h>
#include <stdint.h>

#define B_   16
#define LK_  2048
#define LQ_  256
#define DIM_ 512
#define H_   8
#define DK_  64
#define M_   (B_ * LQ_)     // 4096

// ---------------- helpers ----------------
__device__ __forceinline__ uint32_t pack_h2(float x, float y) {
    __half2 h = __float22half2_rn(make_float2(x, y));
    return *(uint32_t*)&h;
}
__device__ __forceinline__ void pack_split_h(float x, float y,
                                             uint32_t& hi, uint32_t& lo) {
    __half2 h = __float22half2_rn(make_float2(x, y));
    float2 hf = __half22float2(h);
    __half2 l = __float22half2_rn(make_float2(x - hf.x, y - hf.y));
    hi = *(uint32_t*)&h;
    lo = *(uint32_t*)&l;
}
__device__ __forceinline__ float ex2f(float x) {
    float r; asm("ex2.approx.f32 %0, %1;" : "=f"(r) : "f"(x)); return r;
}
__device__ __forceinline__ void ldsm4(uint32_t* r, uint32_t addr) {
    asm volatile("ldmatrix.sync.aligned.m8n8.x4.shared.b16 {%0,%1,%2,%3}, [%4];"
        : "=r"(r[0]), "=r"(r[1]), "=r"(r[2]), "=r"(r[3]) : "r"(addr));
}
__device__ __forceinline__ void ldsm4t(uint32_t* r, uint32_t addr) {
    asm volatile("ldmatrix.sync.aligned.m8n8.x4.trans.shared.b16 {%0,%1,%2,%3}, [%4];"
        : "=r"(r[0]), "=r"(r[1]), "=r"(r[2]), "=r"(r[3]) : "r"(addr));
}
__device__ __forceinline__ void mma16816(float* c, const uint32_t* a,
                                         uint32_t b0, uint32_t b1) {
    asm volatile("mma.sync.aligned.m16n8k16.row.col.f32.f16.f16.f32 "
        "{%0,%1,%2,%3}, {%4,%5,%6,%7}, {%8,%9}, {%0,%1,%2,%3};"
        : "+f"(c[0]), "+f"(c[1]), "+f"(c[2]), "+f"(c[3])
        : "r"(a[0]), "r"(a[1]), "r"(a[2]), "r"(a[3]), "r"(b0), "r"(b1));
}
__device__ __forceinline__ void cp16(uint32_t dst, const void* src) {
    asm volatile("cp.async.cg.shared.global [%0], [%1], 16;" :: "r"(dst), "l"(src));
}

// ---------------- scratch (__device__ globals) ----------------
__device__ float  g_q  [M_ * DIM_];
__device__ __half g_gh [M_ * DIM_];
__device__ __half g_xh [M_ * DIM_];
__device__ __half g_wqh[DIM_ * DIM_];
__device__ __half g_woh[DIM_ * DIM_], g_wol[DIM_ * DIM_];

// ---------------------------------------------------------------------------
// Prep: G -> fp16; Wq -> fp16 (single); Wo -> fp16 hi/lo
// ---------------------------------------------------------------------------
#define NG (M_ * DIM_ / 2)
#define NW (DIM_ * DIM_ / 2)

__global__ void prep_kernel(const float* __restrict__ G,
                            const float* __restrict__ Wq,
                            const float* __restrict__ Wo) {
    int i = blockIdx.x * blockDim.x + threadIdx.x;
    if (i < NG) {
        float2 v = ((const float2*)G)[i];
        ((uint32_t*)g_gh)[i] = pack_h2(v.x, v.y);
    } else if (i < NG + NW) {
        int j = i - NG;
        float2 v = ((const float2*)Wq)[j];
        ((uint32_t*)g_wqh)[j] = pack_h2(v.x, v.y);
    } else if (i < NG + 2 * NW) {
        int j = i - NG - NW;
        float2 v = ((const float2*)Wo)[j];
        uint32_t h, l;
        pack_split_h(v.x, v.y, h, l);
        ((uint32_t*)g_woh)[j] = h; ((uint32_t*)g_wol)[j] = l;
    }
}

// ---------------------------------------------------------------------------
// GEMM 1-term (Q projection): BM=128, BN=64, BK=32, 3-stage, 36KB smem.
// ---------------------------------------------------------------------------
#define G1_STAGE 12288
#define G1_WH    8192
#define GEMM1_SMEM (3 * G1_STAGE)   // 36 KB

__global__ __launch_bounds__(256, 2)
void gemm1_kernel(const __half* __restrict__ Ah,
                  const __half* __restrict__ Wh,
                  const float* __restrict__ bias,
                  float* __restrict__ C) {
    extern __shared__ char sm[];
    const uint32_t sb = (uint32_t)__cvta_generic_to_shared(sm);
    const int tid = threadIdx.x, wid = tid >> 5, lane = tid & 31;
    const int g = lane >> 2, t = lane & 3;
    const int wm = wid & 3, wn = wid >> 2;
    const int n0 = blockIdx.x * 64, m0 = blockIdx.y * 128;

    auto issue = [&](int kb, int st) {
        uint32_t base = sb + (uint32_t)st * G1_STAGE;
        #pragma unroll
        for (int i = 0; i < 2; ++i) {
            int lin = tid + i * 256;
            int row = lin >> 2, c = lin & 3;
            uint32_t off = (uint32_t)(row * 64 + c * 16);
            off ^= (off >> 3) & 0x30;
            cp16(base + off, Ah + (size_t)(m0 + row) * DIM_ + kb * 32 + c * 8);
        }
        {
            int row = tid >> 3, c = tid & 7;
            uint32_t off = (uint32_t)(row * 128 + c * 16);
            off ^= (off >> 3) & 0x70;
            cp16(base + G1_WH + off, Wh + (size_t)(kb * 32 + row) * DIM_ + n0 + c * 8);
        }
        asm volatile("cp.async.commit_group;");
    };

    float acc[2][4][4];
    #pragma unroll
    for (int i = 0; i < 2; ++i)
        #pragma unroll
        for (int j = 0; j < 4; ++j)
            #pragma unroll
            for (int r = 0; r < 4; ++r) acc[i][j][r] = 0.f;

    const uint32_t aColByte = (uint32_t)((lane >> 4) * 16);
    const uint32_t xr    = (uint32_t)(lane & 7) << 4;
    const uint32_t wRowB = (uint32_t)((lane & 15) * 128);
    const uint32_t wD    = (uint32_t)((lane >> 4) * 16);
    const uint32_t wCol  = (uint32_t)(wn * 64);

    issue(0, 0);
    issue(1, 1);

    for (int kb = 0; kb < 16; ++kb) {
        asm volatile("cp.async.wait_group 1;");
        __syncthreads();
        if (kb + 2 < 16) issue(kb + 2, (kb + 2) % 3);

        uint32_t base = sb + (uint32_t)(kb % 3) * G1_STAGE;
        #pragma unroll
        for (int s = 0; s < 2; ++s) {
            uint32_t af[2][4];
            #pragma unroll
            for (int mf = 0; mf < 2; ++mf) {
                uint32_t off = (uint32_t)((wm * 32 + mf * 16 + (lane & 15)) * 64)
                             + (uint32_t)(s * 32) + aColByte;
                off ^= (off >> 3) & 0x30;
                ldsm4(af[mf], base + off);
            }
            #pragma unroll
            for (int nq = 0; nq < 2; ++nq) {
                uint32_t wo = (uint32_t)(s * 16 * 128) + wRowB +
                              ((wCol + (uint32_t)(nq * 32) + wD) ^ xr);
                uint32_t bh[4];
                ldsm4t(bh, base + G1_WH + wo);
                #pragma unroll
                for (int mf = 0; mf < 2; ++mf) {
                    mma16816(acc[mf][2 * nq],     af[mf], bh[0], bh[1]);
                    mma16816(acc[mf][2 * nq + 1], af[mf], bh[2], bh[3]);
                }
            }
        }
        __syncthreads();
    }

    #pragma unroll
    for (int mf = 0; mf < 2; ++mf) {
        int r0 = m0 + wm * 32 + mf * 16 + g;
        #pragma unroll
        for (int nj = 0; nj < 4; ++nj) {
            int c = n0 + wn * 32 + nj * 8 + 2 * t;
            float2 bv = *(const float2*)&bias[c];
            *(float2*)&C[(size_t)r0 * DIM_ + c] =
                make_float2(acc[mf][nj][0] + bv.x, acc[mf][nj][1] + bv.y);
            *(float2*)&C[(size_t)(r0 + 8) * DIM_ + c] =
                make_float2(acc[mf][nj][2] + bv.x, acc[mf][nj][3] + bv.y);
        }
    }
}

// ---------------------------------------------------------------------------
// GEMM 2-term hi/lo (output projection) — R9 verified kernel.
// ---------------------------------------------------------------------------
#define G2_STAGE 16384
#define G2_WH    8192
#define G2_WL    12288
#define GEMM2_SMEM (3 * G2_STAGE)   // 48 KB

__global__ __launch_bounds__(256, 2)
void gemm2_kernel(const __half* __restrict__ Ah,
                  const __half* __restrict__ Wh,
                  const __half* __restrict__ Wl,
                  const float* __restrict__ bias,
                  float* __restrict__ C) {
    extern __shared__ char sm[];
    const uint32_t sb = (uint32_t)__cvta_generic_to_shared(sm);
    const int tid = threadIdx.x, wid = tid >> 5, lane = tid & 31;
    const int g = lane >> 2, t = lane & 3;
    const int wm = wid & 3, wn = wid >> 2;
    const int n0 = blockIdx.x * 64, m0 = blockIdx.y * 128;

    auto issue = [&](int kb, int st) {
        uint32_t base = sb + (uint32_t)st * G2_STAGE;
        #pragma unroll
        for (int i = 0; i < 2; ++i) {
            int lin = tid + i * 256;
            int row = lin >> 2, c = lin & 3;
            uint32_t off = (uint32_t)(row * 64 + c * 16);
            off ^= (off >> 3) & 0x30;
            cp16(base + off, Ah + (size_t)(m0 + row) * DIM_ + kb * 32 + c * 8);
        }
        {
            int row = tid >> 3, c = tid & 7;
            uint32_t off = (uint32_t)(row * 128 + c * 16);
            off ^= (off >> 3) & 0x70;
            size_t src = (size_t)(kb * 32 + row) * DIM_ + n0 + c * 8;
            cp16(base + G2_WH + off, Wh + src);
            cp16(base + G2_WL + off, Wl + src);
        }
        asm volatile("cp.async.commit_group;");
    };

    float acc[2][4][4];
    #pragma unroll
    for (int i = 0; i < 2; ++i)
        #pragma unroll
        for (int j = 0; j < 4; ++j)
            #pragma unroll
            for (int r = 0; r < 4; ++r) acc[i][j][r] = 0.f;

    const uint32_t aColByte = (uint32_t)((lane >> 4) * 16);
    const uint32_t xr    = (uint32_t)(lane & 7) << 4;
    const uint32_t wRowB = (uint32_t)((lane & 15) * 128);
    const uint32_t wD    = (uint32_t)((lane >> 4) * 16);
    const uint32_t wCol  = (uint32_t)(wn * 64);

    issue(0, 0);
    issue(1, 1);

    for (int kb = 0; kb < 16; ++kb) {
        asm volatile("cp.async.wait_group 1;");
        __syncthreads();
        if (kb + 2 < 16) issue(kb + 2, (kb + 2) % 3);

        uint32_t base = sb + (uint32_t)(kb % 3) * G2_STAGE;
        #pragma unroll
        for (int s = 0; s < 2; ++s) {
            uint32_t af[2][4];
            #pragma unroll
            for (int mf = 0; mf < 2; ++mf) {
                uint32_t off = (uint32_t)((wm * 32 + mf * 16 + (lane & 15)) * 64)
                             + (uint32_t)(s * 32) + aColByte;
                off ^= (off >> 3) & 0x30;
                ldsm4(af[mf], base + off);
            }
            #pragma unroll
            for (int nq = 0; nq < 2; ++nq) {
                uint32_t wo = (uint32_t)(s * 16 * 128) + wRowB +
                              ((wCol + (uint32_t)(nq * 32) + wD) ^ xr);
                uint32_t bh[4], bl[4];
                ldsm4t(bh, base + G2_WH + wo);
                ldsm4t(bl, base + G2_WL + wo);
                #pragma unroll
                for (int mf = 0; mf < 2; ++mf) {
                    mma16816(acc[mf][2 * nq],     af[mf], bh[0], bh[1]);
                    mma16816(acc[mf][2 * nq + 1], af[mf], bh[2], bh[3]);
                    mma16816(acc[mf][2 * nq],     af[mf], bl[0], bl[1]);
                    mma16816(acc[mf][2 * nq + 1], af[mf], bl[2], bl[3]);
                }
            }
        }
        __syncthreads();
    }

    #pragma unroll
    for (int mf = 0; mf < 2; ++mf) {
        int r0 = m0 + wm * 32 + mf * 16 + g;
        #pragma unroll
        for (int nj = 0; nj < 4; ++nj) {
            int c = n0 + wn * 32 + nj * 8 + 2 * t;
            float2 bv = *(const float2*)&bias[c];
            *(float2*)&C[(size_t)r0 * DIM_ + c] =
                make_float2(acc[mf][nj][0] + bv.x, acc[mf][nj][1] + bv.y);
            *(float2*)&C[(size_t)(r0 + 8) * DIM_ + c] =
                make_float2(acc[mf][nj][2] + bv.x, acc[mf][nj][3] + bv.y);
        }
    }
}

// ---------------------------------------------------------------------------
// FA2 on mma.sync fp16. S in log2 domain, ex2.approx.f32 softmax,
// l via ones-mma; S-loop pair-interleaved (2 independent HMMA chains).
// ---------------------------------------------------------------------------
#define ONES_H2 0x3C003C00u

__global__ __launch_bounds__(256, 2)
void attn_mma_kernel(const float* __restrict__ Lp, const float* __restrict__ Qp,
                     __half* __restrict__ Xh) {
    __shared__ __half KH[2][64 * 64];   // [buf][row][d]

    const int tid  = threadIdx.x;
    const int wid  = tid >> 5;
    const int lane = tid & 31;
    const int g = lane >> 2, t = lane & 3;
    const int qb = blockIdx.x, h = blockIdx.y, b = blockIdx.z;
    const float scale = 0.00552427172801990775f * 1.44269504088896341f;

    const uint32_t khb = (uint32_t)__cvta_generic_to_shared(KH);

    uint32_t qa[4][4];
    {
        const float* qbase =
            Qp + ((size_t)b * LQ_ + (size_t)qb * 128 + wid * 16) * DIM_ + h * DK_;
        #pragma unroll
        for (int s = 0; s < 4; ++s) {
            int d0 = 16 * s + 2 * t;
            float2 v0 = *(const float2*)&qbase[(size_t)g * DIM_ + d0];
            float2 v1 = *(const float2*)&qbase[(size_t)(g + 8) * DIM_ + d0];
            float2 v2 = *(const float2*)&qbase[(size_t)g * DIM_ + d0 + 8];
            float2 v3 = *(const float2*)&qbase[(size_t)(g + 8) * DIM_ + d0 + 8];
            qa[s][0] = pack_h2(v0.x * scale, v0.y * scale);
            qa[s][1] = pack_h2(v1.x * scale, v1.y * scale);
            qa[s][2] = pack_h2(v2.x * scale, v2.y * scale);
            qa[s][3] = pack_h2(v3.x * scale, v3.y * scale);
        }
    }

    const int lr0 = tid >> 4;          // 0..15
    const int ld4 = (tid & 15) * 4;    // 0..60
    const float* lbase = Lp + (size_t)b * LK_ * DIM_ + h * DK_;

    float4 pf[4];
    #pragma unroll
    for (int it = 0; it < 4; ++it)
        pf[it] = *(const float4*)&lbase[(size_t)(lr0 + it * 16) * DIM_ + ld4];

    auto store_half = [&](int buf) {
        #pragma unroll
        for (int it = 0; it < 4; ++it) {
            int r = lr0 + it * 16;
            uint32_t off = (uint32_t)(r * 128 + ld4 * 2);
            off = off ^ ((off >> 3) & 0x70);
            *(uint2*)((char*)KH[buf] + off) =
                make_uint2(pack_h2(pf[it].x, pf[it].y), pack_h2(pf[it].z, pf[it].w));
        }
    };
    auto load_half = [&](int j) {
        #pragma unroll
        for (int it = 0; it < 4; ++it)
            pf[it] = *(const float4*)
                &lbase[(size_t)(j * 64 + lr0 + it * 16) * DIM_ + ld4];
    };

    float oacc[8][4];
    #pragma unroll
    for (int i = 0; i < 8; ++i)
        #pragma unroll
        for (int j = 0; j < 4; ++j) oacc[i][j] = 0.f;
    float lfrag[4] = {0.f, 0.f, 0.f, 0.f};

    const uint32_t sXor  = (uint32_t)(lane & 7) << 4;
    const uint32_t sRow  = (uint32_t)(lane & 7) * 128;
    const uint32_t sOff0 = sRow + ((((uint32_t)(lane >> 3)) * 16 +  0) ^ sXor);
    const uint32_t sOff1 = sRow + ((((uint32_t)(lane >> 3)) * 16 + 64) ^ sXor);
    const uint32_t vRow  = (uint32_t)(lane & 15) * 128;
    const uint32_t vD    = (uint32_t)(lane >> 4) * 16;

    store_half(0);
    load_half(1);
    __syncthreads();

    for (int i = 0; i < 32; ++i) {
        const uint32_t bo = (uint32_t)((i & 1) * 8192);

        // ---- S = Q K^T, nf-pair interleaved (2 independent chains) ----
        float sacc[8][4];
        #pragma unroll
        for (int nf = 0; nf < 8; ++nf) {
            sacc[nf][0] = 0.f; sacc[nf][1] = 0.f;
            sacc[nf][2] = 0.f; sacc[nf][3] = 0.f;
        }
        #pragma unroll
        for (int np = 0; np < 4; ++np) {
            uint32_t bA[8], bB[8];
            uint32_t base0 = khb + bo + (uint32_t)(2 * np * 1024);
            ldsm4(bA + 0, base0 + sOff0);
            ldsm4(bA + 4, base0 + sOff1);
            ldsm4(bB + 0, base0 + 1024 + sOff0);
            ldsm4(bB + 4, base0 + 1024 + sOff1);
            #pragma unroll
            for (int s = 0; s < 4; ++s) {
                mma16816(sacc[2 * np],     qa[s], bA[2 * s], bA[2 * s + 1]);
                mma16816(sacc[2 * np + 1], qa[s], bB[2 * s], bB[2 * s + 1]);
            }
        }

        // ---- P = exp2(S); l += P @ ones; O += P V ----
        #pragma unroll
        for (int u = 0; u < 4; ++u) {
            uint32_t pa[4];
            pa[0] = pack_h2(ex2f(sacc[2 * u][0]),     ex2f(sacc[2 * u][1]));
            pa[1] = pack_h2(ex2f(sacc[2 * u][2]),     ex2f(sacc[2 * u][3]));
            pa[2] = pack_h2(ex2f(sacc[2 * u + 1][0]), ex2f(sacc[2 * u + 1][1]));
            pa[3] = pack_h2(ex2f(sacc[2 * u + 1][2]), ex2f(sacc[2 * u + 1][3]));
            mma16816(lfrag, pa, ONES_H2, ONES_H2);
            #pragma unroll
            for (int dfp = 0; dfp < 4; ++dfp) {
                uint32_t voff = bo + vRow + (uint32_t)(u * 2048)
                              + (((uint32_t)(dfp * 32) + vD) ^ sXor);
                uint32_t vh[4];
                ldsm4t(vh, khb + voff);
                mma16816(oacc[2 * dfp],     pa, vh[0], vh[1]);
                mma16816(oacc[2 * dfp + 1], pa, vh[2], vh[3]);
            }
        }

        if (i < 31) {
            store_half((i + 1) & 1);
            if (i < 30) load_half(i + 2);
            __syncthreads();
        }
    }

    float inv0 = 1.f / lfrag[0], inv1 = 1.f / lfrag[2];

    size_t r0 = ((size_t)b * LQ_ + (size_t)qb * 128 + wid * 16 + g) * DIM_ + h * DK_;
    size_t r1 = r0 + 8 * DIM_;
    #pragma unroll
    for (int df = 0; df < 8; ++df) {
        int c = df * 8 + 2 * t;
        *(uint32_t*)((char*)Xh + (r0 + c) * 2) =
            pack_h2(oacc[df][0] * inv0, oacc[df][1] * inv0);
        *(uint32_t*)((char*)Xh + (r1 + c) * 2) =
            pack_h2(oacc[df][2] * inv1, oacc[df][3] * inv1);
    }
}

// ---------------------------------------------------------------------------
extern "C" void kernel_launch(void* const* d_in, const int* in_sizes, int n_in,
                              void* d_out, int out_size) {
    const float* L  = (const float*)d_in[0];
    const float* G  = (const float*)d_in[1];
    const float* Wq = (const float*)d_in[2];
    const float* bq = (const float*)d_in[3];
    const float* Wo = (const float*)d_in[4];
    const float* bo = (const float*)d_in[5];
    float* out = (float*)d_out;

    float* qbuf;
    __half *gh, *xh, *wqh, *woh, *wol;
    cudaGetSymbolAddress((void**)&qbuf, g_q);
    cudaGetSymbolAddress((void**)&gh,  g_gh);
    cudaGetSymbolAddress((void**)&xh,  g_xh);
    cudaGetSymbolAddress((void**)&wqh, g_wqh);
    cudaGetSymbolAddress((void**)&woh, g_woh);
    cudaGetSymbolAddress((void**)&wol, g_wol);

    cudaFuncSetAttribute(gemm1_kernel,
                         cudaFuncAttributeMaxDynamicSharedMemorySize, GEMM1_SMEM);
    cudaFuncSetAttribute(gemm2_kernel,
                         cudaFuncAttributeMaxDynamicSharedMemorySize, GEMM2_SMEM);

    dim3 gGemm(DIM_ / 64, M_ / 128);            // (8, 32) = 256 CTAs
    dim3 gAttn(LQ_ / 128, H_, B_);              // 256 CTAs
    int prepBlocks = (NG + 2 * NW + 255) / 256;

    prep_kernel<<<prepBlocks, 256>>>(G, Wq, Wo);
    gemm1_kernel<<<gGemm, 256, GEMM1_SMEM>>>(gh, wqh, bq, qbuf);
    attn_mma_kernel<<<gAttn, 256>>>(L, qbuf, xh);
    gemm2_kernel<<<gGemm, 256, GEMM2_SMEM>>>(xh, woh, wol, bo, out);
}